// round 1
// baseline (speedup 1.0000x reference)
#include <cuda_runtime.h>
#include <math.h>

// Problem constants
#define B_  2
#define S_  2048
#define D_  256      // = H_*C_
#define H_  8
#define C_  32
#define OUT_ 256
#define WIN_ 32
#define M_  (B_ * S_)   // 4096 rows for all GEMMs

// -------- device scratch (no allocations allowed) --------
__device__ float g_Q[B_ * S_ * D_];
__device__ float g_K[B_ * S_ * D_];
__device__ float g_V[B_ * S_ * D_];
__device__ float g_G[B_ * S_ * D_];
__device__ float g_O[B_ * S_ * D_];

// ============================================================
// Tiled fp32 GEMM body: Y[m,n] = sum_k X[m,k] * W(k,n)  (K=N=256, M=4096)
// W(k,n) = transW ? W[n*256+k] : W[k*256+n]
// optional bias + sigmoid epilogue.
// BM=64, BN=64, BK=16, 256 threads, 4x4 per thread.
// ============================================================
__device__ __forceinline__ void gemm_body(const float* __restrict__ X,
                                          const float* __restrict__ W,
                                          const float* __restrict__ bias,
                                          float* __restrict__ Y,
                                          int transW, int doSigmoid) {
    __shared__ float As[16][64];   // [k][m]
    __shared__ float Bs[16][64];   // [k][n]

    const int tid = threadIdx.x;          // 0..255
    const int tx  = tid & 15;             // 0..15 (n group)
    const int ty  = tid >> 4;             // 0..15 (m group)
    const int rowBase = blockIdx.y * 64;
    const int colBase = blockIdx.x * 64;

    float acc[4][4];
#pragma unroll
    for (int i = 0; i < 4; i++)
#pragma unroll
        for (int j = 0; j < 4; j++) acc[i][j] = 0.f;

    for (int k0 = 0; k0 < 256; k0 += 16) {
        // load A tile 64x16 (transposed into As[k][m]); 1024 elems / 256 thr
#pragma unroll
        for (int i = 0; i < 4; i++) {
            int idx = tid + i * 256;          // 0..1023
            int m  = idx >> 4;                // 0..63
            int kk = idx & 15;                // 0..15
            As[kk][m] = X[(rowBase + m) * 256 + k0 + kk];
        }
        // load B tile 16x64
#pragma unroll
        for (int i = 0; i < 4; i++) {
            int idx = tid + i * 256;
            int kk = idx >> 6;                // 0..15
            int n  = idx & 63;                // 0..63
            float w = transW ? W[(colBase + n) * 256 + (k0 + kk)]
                             : W[(k0 + kk) * 256 + (colBase + n)];
            Bs[kk][n] = w;
        }
        __syncthreads();

#pragma unroll
        for (int kk = 0; kk < 16; kk++) {
            float a[4], b[4];
#pragma unroll
            for (int i = 0; i < 4; i++) a[i] = As[kk][ty * 4 + i];
#pragma unroll
            for (int j = 0; j < 4; j++) b[j] = Bs[kk][tx * 4 + j];
#pragma unroll
            for (int i = 0; i < 4; i++)
#pragma unroll
                for (int j = 0; j < 4; j++) acc[i][j] = fmaf(a[i], b[j], acc[i][j]);
        }
        __syncthreads();
    }

#pragma unroll
    for (int i = 0; i < 4; i++) {
        int row = rowBase + ty * 4 + i;
#pragma unroll
        for (int j = 0; j < 4; j++) {
            int n = colBase + tx * 4 + j;
            float v = acc[i][j];
            if (bias) v += bias[n];
            if (doSigmoid) v = 1.f / (1.f + expf(-v));
            Y[row * 256 + n] = v;
        }
    }
}

// blockIdx.z selects which projection: 0=Q 1=K 2=V 3=G
__global__ void proj_kernel(const float* __restrict__ Qin,
                            const float* __restrict__ Kin,
                            const float* __restrict__ Vin,
                            const float* __restrict__ QT,
                            const float* __restrict__ KT,
                            const float* __restrict__ VT,
                            const float* __restrict__ GW,
                            const float* __restrict__ Gb) {
    const float* X; const float* W; float* Y;
    int transW = 0, sig = 0; const float* bias = nullptr;
    switch (blockIdx.z) {
        case 0:  X = Qin; W = QT; Y = g_Q; break;
        case 1:  X = Kin; W = KT; Y = g_K; break;
        case 2:  X = Vin; W = VT; Y = g_V; break;
        default: X = Vin; W = GW; Y = g_G; transW = 1; sig = 1; bias = Gb; break;
    }
    gemm_body(X, W, bias, Y, transW, sig);
}

__global__ void out_gemm_kernel(const float* __restrict__ OW,
                                const float* __restrict__ Ob,
                                float* __restrict__ out) {
    gemm_body(g_O, OW, Ob, out, /*transW=*/1, /*sigmoid=*/0);
}

// ============================================================
// Local-window attention.
// grid: (S/32, H, B). block: 1024 threads (32 warps; warp w handles s = s0+w).
// Window per s: t in [s-32, s+32] (65 positions), clipped to [0,S).
// Tile covers trel in [0,96): t = s0 - 32 + trel.
// ============================================================
__global__ void attn_kernel() {
    __shared__ float Ks[96][33];
    __shared__ float Vs[96][33];
    __shared__ float Qs[32][33];
    __shared__ float P [32][96];

    const int b  = blockIdx.z;
    const int h  = blockIdx.y;
    const int s0 = blockIdx.x * 32;
    const int tid  = threadIdx.x;
    const int warp = tid >> 5;
    const int lane = tid & 31;

    // stage K/V window tiles
    for (int i = tid; i < 96 * 32; i += 1024) {
        int trel = i >> 5;
        int c    = i & 31;
        int t    = s0 - 32 + trel;
        float kv = 0.f, vv = 0.f;
        if (t >= 0 && t < S_) {
            int idx = ((b * S_ + t) * H_ + h) * C_ + c;
            kv = g_K[idx];
            vv = g_V[idx];
        }
        Ks[trel][c] = kv;
        Vs[trel][c] = vv;
    }
    // stage Q rows (one per warp)
    {
        int s = s0 + warp;
        Qs[warp][lane] = g_Q[((b * S_ + s) * H_ + h) * C_ + lane];
    }
    __syncthreads();

    const int s = s0 + warp;
    const float rsC = 0.17677669529663689f;  // 1/sqrt(32)

    // scores: lane-per-t, 3 slots (off = lane, lane+32, lane+64; valid off<=64)
    float sc[3];
#pragma unroll
    for (int j = 0; j < 3; j++) {
        int off = lane + 32 * j;
        float v = -1e30f;
        int t = s - WIN_ + off;
        if (off <= 2 * WIN_ && t >= 0 && t < S_) {
            int trel = warp + off;
            float acc = 0.f;
#pragma unroll
            for (int c = 0; c < 32; c++) acc = fmaf(Qs[warp][c], Ks[trel][c], acc);
            v = acc * rsC;
        }
        sc[j] = v;
    }

    // warp softmax over up-to-65 scores
    float mx = fmaxf(sc[0], fmaxf(sc[1], sc[2]));
#pragma unroll
    for (int o = 16; o; o >>= 1) mx = fmaxf(mx, __shfl_xor_sync(0xffffffffu, mx, o));
    float e[3], sum = 0.f;
#pragma unroll
    for (int j = 0; j < 3; j++) {
        e[j] = expf(sc[j] - mx);   // masked -> exp(-huge) = 0
        sum += e[j];
    }
#pragma unroll
    for (int o = 16; o; o >>= 1) sum += __shfl_xor_sync(0xffffffffu, sum, o);
    const float inv = 1.f / sum;
#pragma unroll
    for (int j = 0; j < 3; j++) P[warp][lane + 32 * j] = e[j] * inv;
    __syncwarp();

    // AV: lane-per-c
    const int c = lane;
    float o = 0.f;
#pragma unroll 4
    for (int off = 0; off <= 2 * WIN_; off++) {
        o = fmaf(P[warp][off], Vs[warp + off][c], o);
    }
    int idx = ((b * S_ + s) * H_ + h) * C_ + c;
    g_O[idx] = o * g_G[idx];
}

// ============================================================
extern "C" void kernel_launch(void* const* d_in, const int* in_sizes, int n_in,
                              void* d_out, int out_size) {
    const float* Qin = (const float*)d_in[0];
    const float* Kin = (const float*)d_in[1];
    const float* Vin = (const float*)d_in[2];
    const float* QT  = (const float*)d_in[3];
    const float* KT  = (const float*)d_in[4];
    const float* VT  = (const float*)d_in[5];
    const float* GW  = (const float*)d_in[6];
    const float* Gb  = (const float*)d_in[7];
    const float* OW  = (const float*)d_in[8];
    const float* Ob  = (const float*)d_in[9];
    float* out = (float*)d_out;

    // 1) projections: Q, K, V, G (grid.z selects)
    dim3 pg(256 / 64, M_ / 64, 4);
    proj_kernel<<<pg, 256>>>(Qin, Kin, Vin, QT, KT, VT, GW, Gb);

    // 2) local-window attention -> g_O
    dim3 ag(S_ / 32, H_, B_);
    attn_kernel<<<ag, 1024>>>();

    // 3) output projection -> d_out
    dim3 og(OUT_ / 64, M_ / 64);
    out_gemm_kernel<<<og, 256>>>(OW, Ob, out);
}

// round 3
// speedup vs baseline: 2.0461x; 2.0461x over previous
#include <cuda_runtime.h>
#include <cuda_bf16.h>
#include <math.h>
#include <stdint.h>

// Problem constants
#define B_  2
#define S_  2048
#define D_  256
#define H_  8
#define C_  32
#define OUT_ 256
#define WIN_ 32
#define M_  (B_ * S_)

// -------- device scratch --------
__device__ float g_Q[B_ * S_ * D_];
__device__ float g_K[B_ * S_ * D_];
__device__ float g_V[B_ * S_ * D_];
__device__ float g_G[B_ * S_ * D_];
__device__ float g_O[B_ * S_ * D_];

// ================= helpers =================
__device__ __forceinline__ uint32_t smem_u32(const void* p) {
    uint32_t a;
    asm("{ .reg .u64 t; cvta.to.shared.u64 t, %1; cvt.u32.u64 %0, t; }" : "=r"(a) : "l"(p));
    return a;
}

#define LDM_X4(r, addr) \
    asm volatile("ldmatrix.sync.aligned.m8n8.x4.shared.b16 {%0,%1,%2,%3}, [%4];" \
        : "=r"((r)[0]), "=r"((r)[1]), "=r"((r)[2]), "=r"((r)[3]) : "r"(addr))

#define MMA_BF16(c, a, b) \
    asm volatile("mma.sync.aligned.m16n8k16.row.col.f32.bf16.bf16.f32 " \
        "{%0,%1,%2,%3}, {%4,%5,%6,%7}, {%8,%9}, {%0,%1,%2,%3};" \
        : "+f"((c)[0]), "+f"((c)[1]), "+f"((c)[2]), "+f"((c)[3]) \
        : "r"((a)[0]), "r"((a)[1]), "r"((a)[2]), "r"((a)[3]), "r"((b)[0]), "r"((b)[1]))

// convert 8 consecutive fp32 into hi-bf16x2 words and lo-bf16x2 words
__device__ __forceinline__ void cvt8(const float4 a, const float4 b, uint4& h, uint4& l) {
    float f[8] = {a.x, a.y, a.z, a.w, b.x, b.y, b.z, b.w};
    uint32_t hw[4], lw[4];
#pragma unroll
    for (int i = 0; i < 4; i++) {
        __nv_bfloat162 hi2 = __floats2bfloat162_rn(f[2 * i], f[2 * i + 1]);
        float rx = f[2 * i]     - __bfloat162float(hi2.x);
        float ry = f[2 * i + 1] - __bfloat162float(hi2.y);
        __nv_bfloat162 lo2 = __floats2bfloat162_rn(rx, ry);
        hw[i] = *reinterpret_cast<uint32_t*>(&hi2);
        lw[i] = *reinterpret_cast<uint32_t*>(&lo2);
    }
    h = make_uint4(hw[0], hw[1], hw[2], hw[3]);
    l = make_uint4(lw[0], lw[1], lw[2], lw[3]);
}

// ================= MMA GEMM =================
// Y[m,n] = sum_k X[m,k] * W(k,n),  W(k,n) = transW ? W[n*256+k] : W[k*256+n]
// BM=128, BN=128, BK=64, 8 warps, warp tile 32x64.
// smem: padded bf16 tiles [128 rows][64 k] with 144-byte row stride (hi & lo for A and B).

#define ROW_B   144                    // bytes per smem row (64*2 + 16 pad)
#define TILE_B  (128 * ROW_B)          // 18432
#define SM_AH   0
#define SM_AL   (SM_AH + TILE_B)
#define SM_BH   (SM_AL + TILE_B)
#define SM_BL   (SM_BH + TILE_B)
#define SM_GEMM_TOTAL (SM_BL + TILE_B) // 73728

__device__ __forceinline__ void mma_gemm_body(const float* __restrict__ X,
                                              const float* __restrict__ W,
                                              const float* __restrict__ bias,
                                              float* __restrict__ Y,
                                              int transW, int doSig) {
    extern __shared__ char smem[];
    const uint32_t sb = smem_u32(smem);
    const int tid  = threadIdx.x;
    const int wid  = tid >> 5;
    const int lane = tid & 31;
    const int warp_m = wid & 3;   // 0..3
    const int warp_n = wid >> 2;  // 0..1
    const int m0 = blockIdx.y * 128;
    const int n0 = blockIdx.x * 128;

    float acc[2][8][4];
#pragma unroll
    for (int i = 0; i < 2; i++)
#pragma unroll
        for (int j = 0; j < 8; j++)
#pragma unroll
            for (int q = 0; q < 4; q++) acc[i][j][q] = 0.f;

    // per-thread ldmatrix source addresses (row/chunk pattern shared by A and B)
    const int lm_row   = (lane & 15);
    const int lm_chunk = (lane >> 4) * 16;  // byte offset of k-chunk (8 bf16)

    for (int kc = 0; kc < 4; kc++) {
        const int kb = kc * 64;
        if (kc) __syncthreads();

        // ---- stage A tile (128 x 64) hi/lo ----
#pragma unroll
        for (int it = 0; it < 4; it++) {
            int g  = tid + it * 256;
            int r  = g >> 3, kg = g & 7;
            const float4* p = reinterpret_cast<const float4*>(X + (size_t)(m0 + r) * 256 + kb + kg * 8);
            uint4 h, l;
            cvt8(p[0], p[1], h, l);
            uint32_t off = (uint32_t)(r * ROW_B + kg * 16);
            *reinterpret_cast<uint4*>(smem + SM_AH + off) = h;
            *reinterpret_cast<uint4*>(smem + SM_AL + off) = l;
        }

        // ---- stage B tile as [n][k] (128 x 64) hi/lo ----
        if (transW) {
#pragma unroll
            for (int it = 0; it < 4; it++) {
                int g = tid + it * 256;
                int n = g >> 3, kg = g & 7;
                const float4* p = reinterpret_cast<const float4*>(W + (size_t)(n0 + n) * 256 + kb + kg * 8);
                uint4 h, l;
                cvt8(p[0], p[1], h, l);
                uint32_t off = (uint32_t)(n * ROW_B + kg * 16);
                *reinterpret_cast<uint4*>(smem + SM_BH + off) = h;
                *reinterpret_cast<uint4*>(smem + SM_BL + off) = l;
            }
        } else {
#pragma unroll
            for (int it = 0; it < 4; it++) {
                int g = tid + it * 256;
                int n = g & 127, kg = g >> 7;   // kg 0..7
                float4 v0, v1;
                const float* wp = W + (size_t)(kb + kg * 8) * 256 + n0 + n;
                v0.x = wp[0];    v0.y = wp[256];  v0.z = wp[512];  v0.w = wp[768];
                v1.x = wp[1024]; v1.y = wp[1280]; v1.z = wp[1536]; v1.w = wp[1792];
                uint4 h, l;
                cvt8(v0, v1, h, l);
                uint32_t off = (uint32_t)(n * ROW_B + kg * 16);
                *reinterpret_cast<uint4*>(smem + SM_BH + off) = h;
                *reinterpret_cast<uint4*>(smem + SM_BL + off) = l;
            }
        }
        __syncthreads();

        // ---- compute: 4 k16 steps ----
#pragma unroll
        for (int ks = 0; ks < 4; ks++) {
            const uint32_t kbyte = (uint32_t)(ks * 32 + lm_chunk);
            uint32_t ah[2][4], al[2][4], bh[8][2], bl[8][2];

#pragma unroll
            for (int mf = 0; mf < 2; mf++) {
                uint32_t off = (uint32_t)((warp_m * 32 + mf * 16 + lm_row) * ROW_B) + kbyte;
                LDM_X4(ah[mf], sb + SM_AH + off);
                LDM_X4(al[mf], sb + SM_AL + off);
            }
#pragma unroll
            for (int np = 0; np < 4; np++) {
                uint32_t off = (uint32_t)((warp_n * 64 + np * 16 + lm_row) * ROW_B) + kbyte;
                uint32_t th[4], tl[4];
                LDM_X4(th, sb + SM_BH + off);
                LDM_X4(tl, sb + SM_BL + off);
                bh[np * 2][0] = th[0]; bh[np * 2][1] = th[2];
                bh[np * 2 + 1][0] = th[1]; bh[np * 2 + 1][1] = th[3];
                bl[np * 2][0] = tl[0]; bl[np * 2][1] = tl[2];
                bl[np * 2 + 1][0] = tl[1]; bl[np * 2 + 1][1] = tl[3];
            }

#pragma unroll
            for (int mf = 0; mf < 2; mf++)
#pragma unroll
                for (int nf = 0; nf < 8; nf++) {
                    MMA_BF16(acc[mf][nf], ah[mf], bh[nf]);
                    MMA_BF16(acc[mf][nf], ah[mf], bl[nf]);
                    MMA_BF16(acc[mf][nf], al[mf], bh[nf]);
                }
        }
    }

    // ---- epilogue ----
#pragma unroll
    for (int mf = 0; mf < 2; mf++) {
        int row = m0 + warp_m * 32 + mf * 16 + (lane >> 2);
#pragma unroll
        for (int nf = 0; nf < 8; nf++) {
            int col = n0 + warp_n * 64 + nf * 8 + (lane & 3) * 2;
            float b0 = bias ? bias[col] : 0.f;
            float b1 = bias ? bias[col + 1] : 0.f;
            float v0 = acc[mf][nf][0] + b0;
            float v1 = acc[mf][nf][1] + b1;
            float v2 = acc[mf][nf][2] + b0;
            float v3 = acc[mf][nf][3] + b1;
            if (doSig) {
                v0 = 1.f / (1.f + expf(-v0));
                v1 = 1.f / (1.f + expf(-v1));
                v2 = 1.f / (1.f + expf(-v2));
                v3 = 1.f / (1.f + expf(-v3));
            }
            *reinterpret_cast<float2*>(Y + (size_t)row * 256 + col)       = make_float2(v0, v1);
            *reinterpret_cast<float2*>(Y + (size_t)(row + 8) * 256 + col) = make_float2(v2, v3);
        }
    }
}

// blockIdx.z: 0=Q 1=K 2=V 3=G
__global__ void __launch_bounds__(256)
proj_mma_kernel(const float* __restrict__ Qin, const float* __restrict__ Kin,
                const float* __restrict__ Vin, const float* __restrict__ QT,
                const float* __restrict__ KT,  const float* __restrict__ VT,
                const float* __restrict__ GW,  const float* __restrict__ Gb) {
    const float* X; const float* W; float* Y;
    int transW = 0, sig = 0; const float* bias = nullptr;
    switch (blockIdx.z) {
        case 0:  X = Qin; W = QT; Y = g_Q; break;
        case 1:  X = Kin; W = KT; Y = g_K; break;
        case 2:  X = Vin; W = VT; Y = g_V; break;
        default: X = Vin; W = GW; Y = g_G; transW = 1; sig = 1; bias = Gb; break;
    }
    mma_gemm_body(X, W, bias, Y, transW, sig);
}

__global__ void __launch_bounds__(256)
out_mma_kernel(const float* __restrict__ OW, const float* __restrict__ Ob,
               float* __restrict__ out) {
    mma_gemm_body(g_O, OW, Ob, out, /*transW=*/1, /*sigmoid=*/0);
}

// ================= local-window attention =================
__global__ void attn_kernel() {
    __shared__ float Ks[96][33];
    __shared__ float Vs[96][33];
    __shared__ float Qs[32][33];
    __shared__ float P [32][96];

    const int b  = blockIdx.z;
    const int h  = blockIdx.y;
    const int s0 = blockIdx.x * 32;
    const int tid  = threadIdx.x;
    const int warp = tid >> 5;
    const int lane = tid & 31;

    for (int i = tid; i < 96 * 32; i += 1024) {
        int trel = i >> 5;
        int c    = i & 31;
        int t    = s0 - 32 + trel;
        float kv = 0.f, vv = 0.f;
        if (t >= 0 && t < S_) {
            int idx = ((b * S_ + t) * H_ + h) * C_ + c;
            kv = g_K[idx];
            vv = g_V[idx];
        }
        Ks[trel][c] = kv;
        Vs[trel][c] = vv;
    }
    {
        int s = s0 + warp;
        Qs[warp][lane] = g_Q[((b * S_ + s) * H_ + h) * C_ + lane];
    }
    __syncthreads();

    const int s = s0 + warp;
    const float rsC = 0.17677669529663689f;

    float sc[3];
#pragma unroll
    for (int j = 0; j < 3; j++) {
        int off = lane + 32 * j;
        float v = -1e30f;
        int t = s - WIN_ + off;
        if (off <= 2 * WIN_ && t >= 0 && t < S_) {
            int trel = warp + off;
            float a = 0.f;
#pragma unroll
            for (int c = 0; c < 32; c++) a = fmaf(Qs[warp][c], Ks[trel][c], a);
            v = a * rsC;
        }
        sc[j] = v;
    }

    float mx = fmaxf(sc[0], fmaxf(sc[1], sc[2]));
#pragma unroll
    for (int o = 16; o; o >>= 1) mx = fmaxf(mx, __shfl_xor_sync(0xffffffffu, mx, o));
    float e[3], sum = 0.f;
#pragma unroll
    for (int j = 0; j < 3; j++) { e[j] = expf(sc[j] - mx); sum += e[j]; }
#pragma unroll
    for (int o = 16; o; o >>= 1) sum += __shfl_xor_sync(0xffffffffu, sum, o);
    const float inv = 1.f / sum;
#pragma unroll
    for (int j = 0; j < 3; j++) P[warp][lane + 32 * j] = e[j] * inv;
    __syncwarp();

    const int c = lane;
    float o = 0.f;
#pragma unroll 4
    for (int off = 0; off <= 2 * WIN_; off++) {
        o = fmaf(P[warp][off], Vs[warp + off][c], o);
    }
    int idx = ((b * S_ + s) * H_ + h) * C_ + c;
    g_O[idx] = o * g_G[idx];
}

// ============================================================
extern "C" void kernel_launch(void* const* d_in, const int* in_sizes, int n_in,
                              void* d_out, int out_size) {
    const float* Qin = (const float*)d_in[0];
    const float* Kin = (const float*)d_in[1];
    const float* Vin = (const float*)d_in[2];
    const float* QT  = (const float*)d_in[3];
    const float* KT  = (const float*)d_in[4];
    const float* VT  = (const float*)d_in[5];
    const float* GW  = (const float*)d_in[6];
    const float* Gb  = (const float*)d_in[7];
    const float* OW  = (const float*)d_in[8];
    const float* Ob  = (const float*)d_in[9];
    float* out = (float*)d_out;

    static int attrs_set = 0;
    if (!attrs_set) {
        cudaFuncSetAttribute(proj_mma_kernel, cudaFuncAttributeMaxDynamicSharedMemorySize, SM_GEMM_TOTAL);
        cudaFuncSetAttribute(out_mma_kernel,  cudaFuncAttributeMaxDynamicSharedMemorySize, SM_GEMM_TOTAL);
        attrs_set = 1;
    }

    // 1) projections on tensor cores (HMMA)
    proj_mma_kernel<<<dim3(2, 32, 4), 256, SM_GEMM_TOTAL>>>(Qin, Kin, Vin, QT, KT, VT, GW, Gb);

    // 2) local-window attention
    attn_kernel<<<dim3(S_ / 32, H_, B_), 1024>>>();

    // 3) output projection
    out_mma_kernel<<<dim3(2, 32, 1), 256, SM_GEMM_TOTAL>>>(OW, Ob, out);
}

// round 4
// speedup vs baseline: 2.5188x; 1.2310x over previous
#include <cuda_runtime.h>
#include <cuda_bf16.h>
#include <math.h>
#include <stdint.h>

#define B_  2
#define S_  2048
#define D_  256
#define H_  8
#define C_  32
#define OUT_ 256
#define WIN_ 32
#define M_  (B_ * S_)

typedef __nv_bfloat16 bf16;

// -------- device scratch (pre-split bf16 hi/lo everywhere) --------
__device__ __align__(16) bf16 g_Xh[3 * M_ * D_];   // Qin,Kin,Vin hi
__device__ __align__(16) bf16 g_Xl[3 * M_ * D_];   // lo
__device__ __align__(16) bf16 g_Wh[5 * 256 * 256]; // 0=QT^T 1=KT^T 2=VT^T 3=GW 4=OW  ([n][k])
__device__ __align__(16) bf16 g_Wl[5 * 256 * 256];
__device__ __align__(16) bf16 g_Qh[M_ * D_], g_Ql[M_ * D_];
__device__ __align__(16) bf16 g_Kh[M_ * D_], g_Kl[M_ * D_];
__device__ __align__(16) bf16 g_Vh[M_ * D_], g_Vl[M_ * D_];
__device__ __align__(16) float g_G[M_ * D_];
__device__ __align__(16) bf16 g_Oh[M_ * D_], g_Ol[M_ * D_];

// ================= helpers =================
__device__ __forceinline__ uint32_t smem_u32(const void* p) {
    uint32_t a;
    asm("{ .reg .u64 t; cvta.to.shared.u64 t, %1; cvt.u32.u64 %0, t; }" : "=r"(a) : "l"(p));
    return a;
}
#define LDM_X4(r, addr) \
    asm volatile("ldmatrix.sync.aligned.m8n8.x4.shared.b16 {%0,%1,%2,%3}, [%4];" \
        : "=r"((r)[0]), "=r"((r)[1]), "=r"((r)[2]), "=r"((r)[3]) : "r"(addr))
#define LDM_X2(r, addr) \
    asm volatile("ldmatrix.sync.aligned.m8n8.x2.shared.b16 {%0,%1}, [%2];" \
        : "=r"((r)[0]), "=r"((r)[1]) : "r"(addr))
#define MMA_BF16(c, a, b) \
    asm volatile("mma.sync.aligned.m16n8k16.row.col.f32.bf16.bf16.f32 " \
        "{%0,%1,%2,%3}, {%4,%5,%6,%7}, {%8,%9}, {%0,%1,%2,%3};" \
        : "+f"((c)[0]), "+f"((c)[1]), "+f"((c)[2]), "+f"((c)[3]) \
        : "r"((a)[0]), "r"((a)[1]), "r"((a)[2]), "r"((a)[3]), "r"((b)[0]), "r"((b)[1]))
#define CP_ASYNC16(dst, src) \
    asm volatile("cp.async.cg.shared.global [%0], [%1], 16;" :: "r"(dst), "l"(src))
#define CP_COMMIT() asm volatile("cp.async.commit_group;" ::: "memory")
#define CP_WAIT(n)  asm volatile("cp.async.wait_group %0;" :: "n"(n) : "memory")

// split one fp32 pair into packed hi/lo bf16x2 words
__device__ __forceinline__ void split2(float a, float b, uint32_t& h, uint32_t& l) {
    __nv_bfloat162 hi2 = __floats2bfloat162_rn(a, b);
    float ra = a - __bfloat162float(hi2.x);
    float rb = b - __bfloat162float(hi2.y);
    __nv_bfloat162 lo2 = __floats2bfloat162_rn(ra, rb);
    h = *reinterpret_cast<uint32_t*>(&hi2);
    l = *reinterpret_cast<uint32_t*>(&lo2);
}

// ================= prep kernels =================
__global__ void prep_inputs(const float* __restrict__ Qin, const float* __restrict__ Kin,
                            const float* __restrict__ Vin) {
    const float* src = (blockIdx.y == 0) ? Qin : (blockIdx.y == 1) ? Kin : Vin;
    size_t base = (size_t)blockIdx.y * (M_ * D_);
    int i = blockIdx.x * 256 + threadIdx.x;     // one float4 each
    float4 v = reinterpret_cast<const float4*>(src)[i];
    uint32_t h0, l0, h1, l1;
    split2(v.x, v.y, h0, l0);
    split2(v.z, v.w, h1, l1);
    reinterpret_cast<uint2*>(g_Xh + base)[i] = make_uint2(h0, h1);
    reinterpret_cast<uint2*>(g_Xl + base)[i] = make_uint2(l0, l1);
}

__global__ void prep_wstraight(const float* __restrict__ GW, const float* __restrict__ OW) {
    const float* src = (blockIdx.y == 0) ? GW : OW;
    size_t base = (size_t)(3 + blockIdx.y) * 65536;
    int i = blockIdx.x * 256 + threadIdx.x;
    float4 v = reinterpret_cast<const float4*>(src)[i];
    uint32_t h0, l0, h1, l1;
    split2(v.x, v.y, h0, l0);
    split2(v.z, v.w, h1, l1);
    reinterpret_cast<uint2*>(g_Wh + base)[i] = make_uint2(h0, h1);
    reinterpret_cast<uint2*>(g_Wl + base)[i] = make_uint2(l0, l1);
}

// transpose [k][n] -> [n][k] with hi/lo split (QT, KT, VT)
__global__ void prep_wtrans(const float* __restrict__ QT, const float* __restrict__ KT,
                            const float* __restrict__ VT) {
    const float* src = (blockIdx.z == 0) ? QT : (blockIdx.z == 1) ? KT : VT;
    size_t base = (size_t)blockIdx.z * 65536;
    __shared__ float t[32][33];
    int tx = threadIdx.x & 31, ty = threadIdx.x >> 5;
    int k0 = blockIdx.y * 32, n0 = blockIdx.x * 32;
#pragma unroll
    for (int r = 0; r < 4; r++)
        t[ty + r * 8][tx] = src[(size_t)(k0 + ty + r * 8) * 256 + n0 + tx];
    __syncthreads();
#pragma unroll
    for (int r = 0; r < 4; r++) {
        int n = n0 + ty + r * 8, k = k0 + tx;
        float v = t[tx][ty + r * 8];
        bf16 h = __float2bfloat16(v);
        bf16 l = __float2bfloat16(v - __bfloat162float(h));
        g_Wh[base + (size_t)n * 256 + k] = h;
        g_Wl[base + (size_t)n * 256 + k] = l;
    }
}

// ================= bf16 MMA GEMM (pre-split inputs) =================
// Y[m,n] = sum_k A[m,k]*B[n,k] (3-term hi/lo). BM=128 BN=128 BK=32, 2-stage cp.async.
#define G_ROW  80                  // 32 bf16 = 64B + 16 pad
#define G_TILE (128 * G_ROW)       // 10240
#define SMEM_GEMM (2 * 4 * G_TILE) // 81920

// MODE: 0 = bf16 hi/lo out, 1 = f32 + bias + sigmoid, 2 = f32 + bias
template <int MODE>
__device__ __forceinline__ void gemm_core(const bf16* __restrict__ Ah, const bf16* __restrict__ Al,
                                          const bf16* __restrict__ Bh, const bf16* __restrict__ Bl,
                                          const float* __restrict__ bias,
                                          float* __restrict__ Yf,
                                          bf16* __restrict__ Yh, bf16* __restrict__ Yl) {
    extern __shared__ char smem[];
    const uint32_t sb = smem_u32(smem);
    const int tid = threadIdx.x, wid = tid >> 5, lane = tid & 31;
    const int warp_m = wid & 3, warp_n = wid >> 2;
    const int m0 = blockIdx.y * 128, n0 = blockIdx.x * 128;
    const int lm_row = lane & 15, lm_chunk = (lane >> 4) * 16;

    const bf16* srcs[4] = {Ah, Al, Bh, Bl};

    float acc[2][8][4];
#pragma unroll
    for (int i = 0; i < 2; i++)
#pragma unroll
        for (int j = 0; j < 8; j++)
#pragma unroll
            for (int q = 0; q < 4; q++) acc[i][j][q] = 0.f;

    // stage chunk kc into buffer buf
    auto stage = [&](int kc, int buf) {
#pragma unroll
        for (int tile = 0; tile < 4; tile++) {
            int rbase = (tile < 2) ? m0 : n0;
            const bf16* src = srcs[tile];
#pragma unroll
            for (int it = 0; it < 2; it++) {
                int task = tid + it * 256;          // 0..511
                int row = task >> 2, ch = task & 3;
                const bf16* s = src + (size_t)(rbase + row) * 256 + kc * 32 + ch * 8;
                uint32_t d = sb + (buf * 4 + tile) * G_TILE + row * G_ROW + ch * 16;
                CP_ASYNC16(d, s);
            }
        }
    };

    stage(0, 0);
    CP_COMMIT();

    for (int kc = 0; kc < 8; kc++) {
        if (kc < 7) {
            stage(kc + 1, (kc + 1) & 1);
            CP_COMMIT();
            CP_WAIT(1);
        } else {
            CP_WAIT(0);
        }
        __syncthreads();

        const uint32_t bb = sb + (kc & 1) * 4 * G_TILE;
#pragma unroll
        for (int ks = 0; ks < 2; ks++) {
            const uint32_t kbyte = ks * 32 + lm_chunk;
            uint32_t ah[2][4], al[2][4], bh[8][2], bl[8][2];
#pragma unroll
            for (int mf = 0; mf < 2; mf++) {
                uint32_t off = (uint32_t)((warp_m * 32 + mf * 16 + lm_row) * G_ROW) + kbyte;
                LDM_X4(ah[mf], bb + 0 * G_TILE + off);
                LDM_X4(al[mf], bb + 1 * G_TILE + off);
            }
#pragma unroll
            for (int np = 0; np < 4; np++) {
                uint32_t off = (uint32_t)((warp_n * 64 + np * 16 + lm_row) * G_ROW) + kbyte;
                uint32_t th[4], tl[4];
                LDM_X4(th, bb + 2 * G_TILE + off);
                LDM_X4(tl, bb + 3 * G_TILE + off);
                bh[np * 2][0] = th[0]; bh[np * 2][1] = th[2];
                bh[np * 2 + 1][0] = th[1]; bh[np * 2 + 1][1] = th[3];
                bl[np * 2][0] = tl[0]; bl[np * 2][1] = tl[2];
                bl[np * 2 + 1][0] = tl[1]; bl[np * 2 + 1][1] = tl[3];
            }
#pragma unroll
            for (int mf = 0; mf < 2; mf++)
#pragma unroll
                for (int nf = 0; nf < 8; nf++) {
                    MMA_BF16(acc[mf][nf], ah[mf], bh[nf]);
                    MMA_BF16(acc[mf][nf], ah[mf], bl[nf]);
                    MMA_BF16(acc[mf][nf], al[mf], bh[nf]);
                }
        }
        __syncthreads();
    }

    // epilogue
#pragma unroll
    for (int mf = 0; mf < 2; mf++) {
        int row = m0 + warp_m * 32 + mf * 16 + (lane >> 2);
#pragma unroll
        for (int nf = 0; nf < 8; nf++) {
            int col = n0 + warp_n * 64 + nf * 8 + (lane & 3) * 2;
            float v0 = acc[mf][nf][0], v1 = acc[mf][nf][1];
            float v2 = acc[mf][nf][2], v3 = acc[mf][nf][3];
            if (MODE != 0) {
                float b0 = bias[col], b1 = bias[col + 1];
                v0 += b0; v1 += b1; v2 += b0; v3 += b1;
                if (MODE == 1) {
                    v0 = 1.f / (1.f + __expf(-v0));
                    v1 = 1.f / (1.f + __expf(-v1));
                    v2 = 1.f / (1.f + __expf(-v2));
                    v3 = 1.f / (1.f + __expf(-v3));
                }
                *reinterpret_cast<float2*>(Yf + (size_t)row * 256 + col)       = make_float2(v0, v1);
                *reinterpret_cast<float2*>(Yf + (size_t)(row + 8) * 256 + col) = make_float2(v2, v3);
            } else {
                uint32_t h0, l0, h1, l1;
                split2(v0, v1, h0, l0);
                split2(v2, v3, h1, l1);
                *reinterpret_cast<uint32_t*>(Yh + (size_t)row * 256 + col)       = h0;
                *reinterpret_cast<uint32_t*>(Yl + (size_t)row * 256 + col)       = l0;
                *reinterpret_cast<uint32_t*>(Yh + (size_t)(row + 8) * 256 + col) = h1;
                *reinterpret_cast<uint32_t*>(Yl + (size_t)(row + 8) * 256 + col) = l1;
            }
        }
    }
}

__global__ void __launch_bounds__(256, 2)
proj_kernel(const float* __restrict__ Gb) {
    int z = blockIdx.z;
    const bf16* Ah; const bf16* Al;
    switch (z) {
        case 0: Ah = g_Xh;                Al = g_Xl;                break;
        case 1: Ah = g_Xh + 1 * M_ * D_;  Al = g_Xl + 1 * M_ * D_;  break;
        default: Ah = g_Xh + 2 * M_ * D_; Al = g_Xl + 2 * M_ * D_;  break; // V and G both use Vin
    }
    int wslot = (z == 3) ? 3 : z;
    const bf16* Bh = g_Wh + (size_t)wslot * 65536;
    const bf16* Bl = g_Wl + (size_t)wslot * 65536;
    if (z == 0)      gemm_core<0>(Ah, Al, Bh, Bl, nullptr, nullptr, g_Qh, g_Ql);
    else if (z == 1) gemm_core<0>(Ah, Al, Bh, Bl, nullptr, nullptr, g_Kh, g_Kl);
    else if (z == 2) gemm_core<0>(Ah, Al, Bh, Bl, nullptr, nullptr, g_Vh, g_Vl);
    else             gemm_core<1>(Ah, Al, Bh, Bl, Gb, g_G, nullptr, nullptr);
}

__global__ void __launch_bounds__(256, 2)
out_kernel(const float* __restrict__ Ob, float* __restrict__ out) {
    gemm_core<2>(g_Oh, g_Ol, g_Wh + 4 * 65536, g_Wl + 4 * 65536, Ob, out, nullptr, nullptr);
}

// ================= tensor-core local-window attention =================
// grid (64, 8, 2), 256 threads. One CTA = (b, h, 32 s-rows).
#define A_QH 0
#define A_QL 2560
#define A_KH 5120
#define A_KL 12800
#define A_VH 20480
#define A_VL 27136
#define A_PH 33792
#define A_PL 40448
#define A_RED 47104
#define A_TOTAL 48128
#define QK_ROW 80    // Q/K smem row stride bytes (32 bf16 + pad)
#define VT_ROW 208   // VT/P smem row stride bytes (96 bf16 + pad)

__global__ void __launch_bounds__(256)
attn_kernel() {
    __shared__ __align__(16) char sm[A_TOTAL];
    const uint32_t sb = smem_u32(sm);
    float* red = reinterpret_cast<float*>(sm + A_RED); // [32][8]

    const int b = blockIdx.z, h = blockIdx.y, s0 = blockIdx.x * 32;
    const int tid = threadIdx.x, wid = tid >> 5, lane = tid & 31;
    const int lm_row = lane & 15, lm_chunk = (lane >> 4) * 16;

    // ---- stage K (96 x 32) hi/lo ----
    for (int i = tid; i < 384; i += 256) {
        int row = i >> 2, ch = i & 3;
        int t = s0 - 32 + row;
        uint4 vh = make_uint4(0, 0, 0, 0), vl = vh;
        if (t >= 0 && t < S_) {
            size_t e = (size_t)(b * S_ + t) * 256 + h * 32 + ch * 8;
            vh = *reinterpret_cast<const uint4*>(g_Kh + e);
            vl = *reinterpret_cast<const uint4*>(g_Kl + e);
        }
        *reinterpret_cast<uint4*>(sm + A_KH + row * QK_ROW + ch * 16) = vh;
        *reinterpret_cast<uint4*>(sm + A_KL + row * QK_ROW + ch * 16) = vl;
    }
    // ---- stage Q (32 x 32) hi/lo ----
    for (int i = tid; i < 128; i += 256) {
        int row = i >> 2, ch = i & 3;
        size_t e = (size_t)(b * S_ + s0 + row) * 256 + h * 32 + ch * 8;
        *reinterpret_cast<uint4*>(sm + A_QH + row * QK_ROW + ch * 16) =
            *reinterpret_cast<const uint4*>(g_Qh + e);
        *reinterpret_cast<uint4*>(sm + A_QL + row * QK_ROW + ch * 16) =
            *reinterpret_cast<const uint4*>(g_Ql + e);
    }
    // ---- stage V transposed: [c][trel] (32 x 96) hi/lo ----
    for (int i = tid; i < 3072; i += 256) {
        int trel = i >> 5, c = i & 31;
        int t = s0 - 32 + trel;
        bf16 vh = __float2bfloat16(0.f), vl = vh;
        if (t >= 0 && t < S_) {
            size_t e = (size_t)(b * S_ + t) * 256 + h * 32 + c;
            vh = g_Vh[e];
            vl = g_Vl[e];
        }
        *reinterpret_cast<bf16*>(sm + A_VH + c * VT_ROW + trel * 2) = vh;
        *reinterpret_cast<bf16*>(sm + A_VL + c * VT_ROW + trel * 2) = vl;
    }
    __syncthreads();

    // ---- scores: S = Q*K^T, warp w: mf = w>>2, nf = 3*(w&3)+j ----
    const int mf = wid >> 2;
    const int nfb = (wid & 3) * 3;
    float sc[3][4];
#pragma unroll
    for (int j = 0; j < 3; j++)
#pragma unroll
        for (int q = 0; q < 4; q++) sc[j][q] = 0.f;

#pragma unroll
    for (int kf = 0; kf < 2; kf++) {
        uint32_t ah[4], al[4];
        uint32_t aoff = (uint32_t)((mf * 16 + lm_row) * QK_ROW) + kf * 32 + lm_chunk;
        LDM_X4(ah, sb + A_QH + aoff);
        LDM_X4(al, sb + A_QL + aoff);
#pragma unroll
        for (int j = 0; j < 3; j++) {
            uint32_t bh[2], bl[2];
            uint32_t boff = (uint32_t)(((nfb + j) * 8 + (lane & 7)) * QK_ROW) + kf * 32 +
                            (((lane >> 3) & 1) * 16);
            LDM_X2(bh, sb + A_KH + boff);
            LDM_X2(bl, sb + A_KL + boff);
            MMA_BF16(sc[j], ah, bh);
            MMA_BF16(sc[j], ah, bl);
            MMA_BF16(sc[j], al, bh);
        }
    }

    // ---- mask + softmax ----
    const float rsC = 0.17677669529663689f; // 1/sqrt(32)
    const int r0 = mf * 16 + (lane >> 2);
    const int r1 = r0 + 8;
    float sv[3][4];
#pragma unroll
    for (int j = 0; j < 3; j++) {
        int nb = (nfb + j) * 8 + (lane & 3) * 2;
#pragma unroll
        for (int q = 0; q < 4; q++) {
            int n = nb + (q & 1);
            int row = (q < 2) ? r0 : r1;
            int t = s0 - 32 + n;
            bool ok = (n >= row) && (n <= row + 64) && (t >= 0) && (t < S_);
            sv[j][q] = ok ? sc[j][q] * rsC : -1e30f;
        }
    }
    float m0 = -1e30f, m1 = -1e30f;
#pragma unroll
    for (int j = 0; j < 3; j++) {
        m0 = fmaxf(m0, fmaxf(sv[j][0], sv[j][1]));
        m1 = fmaxf(m1, fmaxf(sv[j][2], sv[j][3]));
    }
    m0 = fmaxf(m0, __shfl_xor_sync(0xffffffffu, m0, 1));
    m0 = fmaxf(m0, __shfl_xor_sync(0xffffffffu, m0, 2));
    m1 = fmaxf(m1, __shfl_xor_sync(0xffffffffu, m1, 1));
    m1 = fmaxf(m1, __shfl_xor_sync(0xffffffffu, m1, 2));
    if ((lane & 3) == 0) {
        red[r0 * 8 + (wid & 3)] = m0;
        red[r1 * 8 + (wid & 3)] = m1;
    }
    __syncthreads();
    float mx0 = fmaxf(fmaxf(red[r0 * 8 + 0], red[r0 * 8 + 1]),
                      fmaxf(red[r0 * 8 + 2], red[r0 * 8 + 3]));
    float mx1 = fmaxf(fmaxf(red[r1 * 8 + 0], red[r1 * 8 + 1]),
                      fmaxf(red[r1 * 8 + 2], red[r1 * 8 + 3]));
    float e[3][4], sum0 = 0.f, sum1 = 0.f;
#pragma unroll
    for (int j = 0; j < 3; j++) {
        e[j][0] = __expf(sv[j][0] - mx0);
        e[j][1] = __expf(sv[j][1] - mx0);
        e[j][2] = __expf(sv[j][2] - mx1);
        e[j][3] = __expf(sv[j][3] - mx1);
        sum0 += e[j][0] + e[j][1];
        sum1 += e[j][2] + e[j][3];
    }
    sum0 += __shfl_xor_sync(0xffffffffu, sum0, 1);
    sum0 += __shfl_xor_sync(0xffffffffu, sum0, 2);
    sum1 += __shfl_xor_sync(0xffffffffu, sum1, 1);
    sum1 += __shfl_xor_sync(0xffffffffu, sum1, 2);
    if ((lane & 3) == 0) {
        red[r0 * 8 + 4 + (wid & 3)] = sum0;
        red[r1 * 8 + 4 + (wid & 3)] = sum1;
    }
    __syncthreads();
    float inv0 = 1.f / (red[r0 * 8 + 4] + red[r0 * 8 + 5] + red[r0 * 8 + 6] + red[r0 * 8 + 7]);
    float inv1 = 1.f / (red[r1 * 8 + 4] + red[r1 * 8 + 5] + red[r1 * 8 + 6] + red[r1 * 8 + 7]);

    // P -> smem hi/lo
#pragma unroll
    for (int j = 0; j < 3; j++) {
        int nb = (nfb + j) * 8 + (lane & 3) * 2;
        uint32_t h0, l0, h1, l1;
        split2(e[j][0] * inv0, e[j][1] * inv0, h0, l0);
        split2(e[j][2] * inv1, e[j][3] * inv1, h1, l1);
        *reinterpret_cast<uint32_t*>(sm + A_PH + r0 * VT_ROW + nb * 2) = h0;
        *reinterpret_cast<uint32_t*>(sm + A_PL + r0 * VT_ROW + nb * 2) = l0;
        *reinterpret_cast<uint32_t*>(sm + A_PH + r1 * VT_ROW + nb * 2) = h1;
        *reinterpret_cast<uint32_t*>(sm + A_PL + r1 * VT_ROW + nb * 2) = l1;
    }
    __syncthreads();

    // ---- O = P*V : warp w -> (mf = w>>2, nc = w&3) tile 16x8 ----
    const int nc = wid & 3;
    float oacc[4] = {0.f, 0.f, 0.f, 0.f};
#pragma unroll
    for (int kf = 0; kf < 6; kf++) {
        uint32_t ph[4], pl[4], vh[2], vl[2];
        uint32_t poff = (uint32_t)((mf * 16 + lm_row) * VT_ROW) + kf * 32 + lm_chunk;
        LDM_X4(ph, sb + A_PH + poff);
        LDM_X4(pl, sb + A_PL + poff);
        uint32_t voff = (uint32_t)((nc * 8 + (lane & 7)) * VT_ROW) + kf * 32 +
                        (((lane >> 3) & 1) * 16);
        LDM_X2(vh, sb + A_VH + voff);
        LDM_X2(vl, sb + A_VL + voff);
        MMA_BF16(oacc, ph, vh);
        MMA_BF16(oacc, ph, vl);
        MMA_BF16(oacc, pl, vh);
    }

    // ---- epilogue: gate by G, split hi/lo, store ----
    {
        int gcol = h * 32 + nc * 8 + (lane & 3) * 2;
        size_t e0 = (size_t)(b * S_ + s0 + r0) * 256 + gcol;
        size_t e1 = (size_t)(b * S_ + s0 + r1) * 256 + gcol;
        float2 gA = *reinterpret_cast<const float2*>(g_G + e0);
        float2 gB = *reinterpret_cast<const float2*>(g_G + e1);
        uint32_t h0, l0, h1, l1;
        split2(oacc[0] * gA.x, oacc[1] * gA.y, h0, l0);
        split2(oacc[2] * gB.x, oacc[3] * gB.y, h1, l1);
        *reinterpret_cast<uint32_t*>(g_Oh + e0) = h0;
        *reinterpret_cast<uint32_t*>(g_Ol + e0) = l0;
        *reinterpret_cast<uint32_t*>(g_Oh + e1) = h1;
        *reinterpret_cast<uint32_t*>(g_Ol + e1) = l1;
    }
}

// ============================================================
extern "C" void kernel_launch(void* const* d_in, const int* in_sizes, int n_in,
                              void* d_out, int out_size) {
    const float* Qin = (const float*)d_in[0];
    const float* Kin = (const float*)d_in[1];
    const float* Vin = (const float*)d_in[2];
    const float* QT  = (const float*)d_in[3];
    const float* KT  = (const float*)d_in[4];
    const float* VT  = (const float*)d_in[5];
    const float* GW  = (const float*)d_in[6];
    const float* Gb  = (const float*)d_in[7];
    const float* OW  = (const float*)d_in[8];
    const float* Ob  = (const float*)d_in[9];
    float* out = (float*)d_out;

    cudaFuncSetAttribute(proj_kernel, cudaFuncAttributeMaxDynamicSharedMemorySize, SMEM_GEMM);
    cudaFuncSetAttribute(out_kernel,  cudaFuncAttributeMaxDynamicSharedMemorySize, SMEM_GEMM);

    prep_inputs<<<dim3(M_ * D_ / 1024, 3), 256>>>(Qin, Kin, Vin);
    prep_wstraight<<<dim3(64, 2), 256>>>(GW, OW);
    prep_wtrans<<<dim3(8, 8, 3), 256>>>(QT, KT, VT);

    proj_kernel<<<dim3(2, 32, 4), 256, SMEM_GEMM>>>(Gb);
    attn_kernel<<<dim3(S_ / 32, H_, B_), 256>>>();
    out_kernel<<<dim3(2, 32, 1), 256, SMEM_GEMM>>>(Ob, out);
}

// round 5
// speedup vs baseline: 3.3223x; 1.3190x over previous
#include <cuda_runtime.h>
#include <cuda_fp16.h>
#include <math.h>
#include <stdint.h>

#define B_  2
#define S_  2048
#define D_  256
#define H_  8
#define C_  32
#define OUT_ 256
#define WIN_ 32
#define M_  (B_ * S_)

// -------- device scratch --------
__device__ __align__(16) __half g_Ah[3 * M_ * D_];   // Qin,Kin,Vin hi
__device__ __align__(16) __half g_Al[3 * M_ * D_];   // lo
__device__ __align__(16) __half g_W [5 * 256 * 256]; // 0=QT^T 1=KT^T 2=VT^T 3=GW 4=OW ([n][k]) single fp16
__device__ __align__(16) __half g_Qh[M_ * D_], g_Ql[M_ * D_];
__device__ __align__(16) __half g_K [M_ * D_];
__device__ __align__(16) __half g_V [M_ * D_];
__device__ __align__(16) float  g_G [M_ * D_];
__device__ __align__(16) __half g_Oh[M_ * D_], g_Ol[M_ * D_];

// ================= helpers =================
__device__ __forceinline__ uint32_t smem_u32(const void* p) {
    uint32_t a;
    asm("{ .reg .u64 t; cvta.to.shared.u64 t, %1; cvt.u32.u64 %0, t; }" : "=r"(a) : "l"(p));
    return a;
}
#define LDM_X4(r, addr) \
    asm volatile("ldmatrix.sync.aligned.m8n8.x4.shared.b16 {%0,%1,%2,%3}, [%4];" \
        : "=r"((r)[0]), "=r"((r)[1]), "=r"((r)[2]), "=r"((r)[3]) : "r"(addr))
#define LDM_X2(r, addr) \
    asm volatile("ldmatrix.sync.aligned.m8n8.x2.shared.b16 {%0,%1}, [%2];" \
        : "=r"((r)[0]), "=r"((r)[1]) : "r"(addr))
#define MMA_F16(c, a, b) \
    asm volatile("mma.sync.aligned.m16n8k16.row.col.f32.f16.f16.f32 " \
        "{%0,%1,%2,%3}, {%4,%5,%6,%7}, {%8,%9}, {%0,%1,%2,%3};" \
        : "+f"((c)[0]), "+f"((c)[1]), "+f"((c)[2]), "+f"((c)[3]) \
        : "r"((a)[0]), "r"((a)[1]), "r"((a)[2]), "r"((a)[3]), "r"((b)[0]), "r"((b)[1]))
#define CP_ASYNC16(dst, src) \
    asm volatile("cp.async.cg.shared.global [%0], [%1], 16;" :: "r"(dst), "l"(src))
#define CP_COMMIT() asm volatile("cp.async.commit_group;" ::: "memory")
#define CP_WAIT(n)  asm volatile("cp.async.wait_group %0;" :: "n"(n) : "memory")

// split fp32 pair into packed hi/lo half2 words
__device__ __forceinline__ void split2h(float a, float b, uint32_t& h, uint32_t& l) {
    __half2 hi2 = __floats2half2_rn(a, b);
    float ra = a - __low2float(hi2);
    float rb = b - __high2float(hi2);
    __half2 lo2 = __floats2half2_rn(ra, rb);
    h = *reinterpret_cast<uint32_t*>(&hi2);
    l = *reinterpret_cast<uint32_t*>(&lo2);
}

// ================= prep kernels =================
__global__ void prep_inputs(const float* __restrict__ Qin, const float* __restrict__ Kin,
                            const float* __restrict__ Vin) {
    const float* src = (blockIdx.y == 0) ? Qin : (blockIdx.y == 1) ? Kin : Vin;
    size_t base = (size_t)blockIdx.y * (M_ * D_);
    int i = blockIdx.x * 256 + threadIdx.x;
    float4 v = reinterpret_cast<const float4*>(src)[i];
    uint32_t h0, l0, h1, l1;
    split2h(v.x, v.y, h0, l0);
    split2h(v.z, v.w, h1, l1);
    reinterpret_cast<uint2*>(g_Ah + base)[i] = make_uint2(h0, h1);
    reinterpret_cast<uint2*>(g_Al + base)[i] = make_uint2(l0, l1);
}

__global__ void prep_wstraight(const float* __restrict__ GW, const float* __restrict__ OW) {
    const float* src = (blockIdx.y == 0) ? GW : OW;
    size_t base = (size_t)(3 + blockIdx.y) * 65536;
    int i = blockIdx.x * 256 + threadIdx.x;
    float4 v = reinterpret_cast<const float4*>(src)[i];
    __half2 a = __floats2half2_rn(v.x, v.y);
    __half2 b = __floats2half2_rn(v.z, v.w);
    reinterpret_cast<uint2*>(g_W + base)[i] =
        make_uint2(*reinterpret_cast<uint32_t*>(&a), *reinterpret_cast<uint32_t*>(&b));
}

// transpose [k][n] -> [n][k], single fp16 (QT, KT, VT)
__global__ void prep_wtrans(const float* __restrict__ QT, const float* __restrict__ KT,
                            const float* __restrict__ VT) {
    const float* src = (blockIdx.z == 0) ? QT : (blockIdx.z == 1) ? KT : VT;
    size_t base = (size_t)blockIdx.z * 65536;
    __shared__ float t[32][33];
    int tx = threadIdx.x & 31, ty = threadIdx.x >> 5;
    int k0 = blockIdx.y * 32, n0 = blockIdx.x * 32;
#pragma unroll
    for (int r = 0; r < 4; r++)
        t[ty + r * 8][tx] = src[(size_t)(k0 + ty + r * 8) * 256 + n0 + tx];
    __syncthreads();
#pragma unroll
    for (int r = 0; r < 4; r++) {
        int n = n0 + ty + r * 8, k = k0 + tx;
        g_W[base + (size_t)n * 256 + k] = __float2half(t[tx][ty + r * 8]);
    }
}

// ================= fp16 MMA GEMM (A split hi/lo, B single) =================
#define G_ROW  80
// MODE: 0 = split half out, 1 = f32+bias+sigmoid, 2 = f32+bias, 3 = single half out
template <int MODE, int BM>
__device__ __forceinline__ void gemm_core(const __half* __restrict__ Ah, const __half* __restrict__ Al,
                                          const __half* __restrict__ Bn,
                                          const float* __restrict__ bias,
                                          float* __restrict__ Yf,
                                          __half* __restrict__ Yh, __half* __restrict__ Yl) {
    extern __shared__ char smem[];
    const uint32_t sb = smem_u32(smem);
    const int tid = threadIdx.x, wid = tid >> 5, lane = tid & 31;

    constexpr int WMS = BM / 32;          // warps along M
    constexpr int WNS = 8 / WMS;          // warps along N
    constexpr int NF  = (128 / WNS) / 8;  // 8x8 n-frags per warp
    constexpr int ACH = BM * 4;           // 16B chunks per A tile
    constexpr int STAGE = (2 * BM + 128) * G_ROW;

    const int warp_m = wid % WMS, warp_n = wid / WMS;
    const int m0 = blockIdx.y * BM, n0 = blockIdx.x * 128;
    const int lm_row = lane & 15, lm_chunk = (lane >> 4) * 16;

    float acc[2][NF][4];
#pragma unroll
    for (int i = 0; i < 2; i++)
#pragma unroll
        for (int j = 0; j < NF; j++)
#pragma unroll
            for (int q = 0; q < 4; q++) acc[i][j][q] = 0.f;

    auto stage = [&](int kc, int buf) {
#pragma unroll
        for (int task = tid; task < 2 * ACH + 512; task += 256) {
            const __half* s;
            uint32_t dbase;
            int row, ch;
            if (task < ACH) {
                row = task >> 2; ch = task & 3;
                s = Ah + (size_t)(m0 + row) * 256 + kc * 32 + ch * 8;
                dbase = 0;
            } else if (task < 2 * ACH) {
                int t2 = task - ACH;
                row = t2 >> 2; ch = t2 & 3;
                s = Al + (size_t)(m0 + row) * 256 + kc * 32 + ch * 8;
                dbase = BM * G_ROW;
            } else {
                int t2 = task - 2 * ACH;
                row = t2 >> 2; ch = t2 & 3;
                s = Bn + (size_t)(n0 + row) * 256 + kc * 32 + ch * 8;
                dbase = 2 * BM * G_ROW;
            }
            CP_ASYNC16(sb + buf * STAGE + dbase + row * G_ROW + ch * 16, s);
        }
    };

    stage(0, 0);
    CP_COMMIT();

    for (int kc = 0; kc < 8; kc++) {
        if (kc < 7) {
            stage(kc + 1, (kc + 1) & 1);
            CP_COMMIT();
            CP_WAIT(1);
        } else {
            CP_WAIT(0);
        }
        __syncthreads();

        const uint32_t bb = sb + (kc & 1) * STAGE;
#pragma unroll
        for (int ks = 0; ks < 2; ks++) {
            const uint32_t kbyte = ks * 32 + lm_chunk;
            uint32_t ah[2][4], al[2][4], bfr[NF][2];
#pragma unroll
            for (int mf = 0; mf < 2; mf++) {
                uint32_t off = (uint32_t)((warp_m * 32 + mf * 16 + lm_row) * G_ROW) + kbyte;
                LDM_X4(ah[mf], bb + off);
                LDM_X4(al[mf], bb + BM * G_ROW + off);
            }
#pragma unroll
            for (int np = 0; np < NF / 2; np++) {
                uint32_t off = (uint32_t)((warp_n * NF * 8 + np * 16 + lm_row) * G_ROW) + kbyte;
                uint32_t th[4];
                LDM_X4(th, bb + 2 * BM * G_ROW + off);
                bfr[np * 2][0] = th[0]; bfr[np * 2][1] = th[2];
                bfr[np * 2 + 1][0] = th[1]; bfr[np * 2 + 1][1] = th[3];
            }
#pragma unroll
            for (int mf = 0; mf < 2; mf++)
#pragma unroll
                for (int nf = 0; nf < NF; nf++) {
                    MMA_F16(acc[mf][nf], ah[mf], bfr[nf]);
                    MMA_F16(acc[mf][nf], al[mf], bfr[nf]);
                }
        }
        __syncthreads();
    }

    // epilogue
#pragma unroll
    for (int mf = 0; mf < 2; mf++) {
        int row = m0 + warp_m * 32 + mf * 16 + (lane >> 2);
#pragma unroll
        for (int nf = 0; nf < NF; nf++) {
            int col = n0 + warp_n * NF * 8 + nf * 8 + (lane & 3) * 2;
            float v0 = acc[mf][nf][0], v1 = acc[mf][nf][1];
            float v2 = acc[mf][nf][2], v3 = acc[mf][nf][3];
            if (MODE == 1 || MODE == 2) {
                float b0 = bias[col], b1 = bias[col + 1];
                v0 += b0; v1 += b1; v2 += b0; v3 += b1;
                if (MODE == 1) {
                    v0 = 1.f / (1.f + __expf(-v0));
                    v1 = 1.f / (1.f + __expf(-v1));
                    v2 = 1.f / (1.f + __expf(-v2));
                    v3 = 1.f / (1.f + __expf(-v3));
                }
                *reinterpret_cast<float2*>(Yf + (size_t)row * 256 + col)       = make_float2(v0, v1);
                *reinterpret_cast<float2*>(Yf + (size_t)(row + 8) * 256 + col) = make_float2(v2, v3);
            } else if (MODE == 0) {
                uint32_t h0, l0, h1, l1;
                split2h(v0, v1, h0, l0);
                split2h(v2, v3, h1, l1);
                *reinterpret_cast<uint32_t*>(Yh + (size_t)row * 256 + col)       = h0;
                *reinterpret_cast<uint32_t*>(Yl + (size_t)row * 256 + col)       = l0;
                *reinterpret_cast<uint32_t*>(Yh + (size_t)(row + 8) * 256 + col) = h1;
                *reinterpret_cast<uint32_t*>(Yl + (size_t)(row + 8) * 256 + col) = l1;
            } else {
                __half2 a = __floats2half2_rn(v0, v1);
                __half2 b = __floats2half2_rn(v2, v3);
                *reinterpret_cast<uint32_t*>(Yh + (size_t)row * 256 + col)       = *reinterpret_cast<uint32_t*>(&a);
                *reinterpret_cast<uint32_t*>(Yh + (size_t)(row + 8) * 256 + col) = *reinterpret_cast<uint32_t*>(&b);
            }
        }
    }
}

#define SMEM_PROJ (2 * (2 * 128 + 128) * G_ROW)  // 61440
#define SMEM_OUT  (2 * (2 * 64 + 128) * G_ROW)   // 40960

__global__ void __launch_bounds__(256, 2)
proj_kernel(const float* __restrict__ Gb) {
    int z = blockIdx.z;
    int xslot = (z == 3) ? 2 : z;   // G uses Vin
    const __half* Ah = g_Ah + (size_t)xslot * (M_ * D_);
    const __half* Al = g_Al + (size_t)xslot * (M_ * D_);
    const __half* Bn = g_W + (size_t)z * 65536;
    if (z == 0)      gemm_core<0, 128>(Ah, Al, Bn, nullptr, nullptr, g_Qh, g_Ql);
    else if (z == 1) gemm_core<3, 128>(Ah, Al, Bn, nullptr, nullptr, g_K, nullptr);
    else if (z == 2) gemm_core<3, 128>(Ah, Al, Bn, nullptr, nullptr, g_V, nullptr);
    else             gemm_core<1, 128>(Ah, Al, Bn, Gb, g_G, nullptr, nullptr);
}

__global__ void __launch_bounds__(256, 2)
out_kernel(const float* __restrict__ Ob, float* __restrict__ out) {
    gemm_core<2, 64>(g_Oh, g_Ol, g_W + 4 * 65536, Ob, out, nullptr, nullptr);
}

// ================= fp16 tensor-core local-window attention =================
#define A_QH 0
#define A_QL 2560
#define A_K  5120
#define A_VT 12800
#define A_PH 19456
#define A_PL 26112
#define A_RED 32768
#define A_TOTAL 33792
#define QK_ROW 80
#define VT_ROW 208

__global__ void __launch_bounds__(256)
attn_kernel() {
    __shared__ __align__(16) char sm[A_TOTAL];
    const uint32_t sb = smem_u32(sm);
    float* red = reinterpret_cast<float*>(sm + A_RED); // [32][8]

    const int b = blockIdx.z, h = blockIdx.y, s0 = blockIdx.x * 32;
    const int tid = threadIdx.x, wid = tid >> 5, lane = tid & 31;
    const int lm_row = lane & 15, lm_chunk = (lane >> 4) * 16;

    // stage K (96 x 32) single
    for (int i = tid; i < 384; i += 256) {
        int row = i >> 2, ch = i & 3;
        int t = s0 - 32 + row;
        uint4 v = make_uint4(0, 0, 0, 0);
        if (t >= 0 && t < S_)
            v = *reinterpret_cast<const uint4*>(g_K + (size_t)(b * S_ + t) * 256 + h * 32 + ch * 8);
        *reinterpret_cast<uint4*>(sm + A_K + row * QK_ROW + ch * 16) = v;
    }
    // stage Q (32 x 32) hi/lo
    for (int i = tid; i < 128; i += 256) {
        int row = i >> 2, ch = i & 3;
        size_t e = (size_t)(b * S_ + s0 + row) * 256 + h * 32 + ch * 8;
        *reinterpret_cast<uint4*>(sm + A_QH + row * QK_ROW + ch * 16) =
            *reinterpret_cast<const uint4*>(g_Qh + e);
        *reinterpret_cast<uint4*>(sm + A_QL + row * QK_ROW + ch * 16) =
            *reinterpret_cast<const uint4*>(g_Ql + e);
    }
    // stage V transposed [c][trel] (32 x 96) single
    for (int i = tid; i < 3072; i += 256) {
        int trel = i >> 5, c = i & 31;
        int t = s0 - 32 + trel;
        __half v = __float2half(0.f);
        if (t >= 0 && t < S_) v = g_V[(size_t)(b * S_ + t) * 256 + h * 32 + c];
        *reinterpret_cast<__half*>(sm + A_VT + c * VT_ROW + trel * 2) = v;
    }
    __syncthreads();

    // S = Q*K^T
    const int mf = wid >> 2;
    const int nfb = (wid & 3) * 3;
    float sc[3][4];
#pragma unroll
    for (int j = 0; j < 3; j++)
#pragma unroll
        for (int q = 0; q < 4; q++) sc[j][q] = 0.f;

#pragma unroll
    for (int kf = 0; kf < 2; kf++) {
        uint32_t qh[4], ql[4];
        uint32_t aoff = (uint32_t)((mf * 16 + lm_row) * QK_ROW) + kf * 32 + lm_chunk;
        LDM_X4(qh, sb + A_QH + aoff);
        LDM_X4(ql, sb + A_QL + aoff);
#pragma unroll
        for (int j = 0; j < 3; j++) {
            uint32_t kk[2];
            uint32_t boff = (uint32_t)(((nfb + j) * 8 + (lane & 7)) * QK_ROW) + kf * 32 +
                            (((lane >> 3) & 1) * 16);
            LDM_X2(kk, sb + A_K + boff);
            MMA_F16(sc[j], qh, kk);
            MMA_F16(sc[j], ql, kk);
        }
    }

    // mask + softmax
    const float rsC = 0.17677669529663689f;
    const int r0 = mf * 16 + (lane >> 2);
    const int r1 = r0 + 8;
    float sv[3][4];
#pragma unroll
    for (int j = 0; j < 3; j++) {
        int nb = (nfb + j) * 8 + (lane & 3) * 2;
#pragma unroll
        for (int q = 0; q < 4; q++) {
            int n = nb + (q & 1);
            int row = (q < 2) ? r0 : r1;
            int t = s0 - 32 + n;
            bool ok = (n >= row) && (n <= row + 64) && (t >= 0) && (t < S_);
            sv[j][q] = ok ? sc[j][q] * rsC : -1e30f;
        }
    }
    float m0 = -1e30f, m1 = -1e30f;
#pragma unroll
    for (int j = 0; j < 3; j++) {
        m0 = fmaxf(m0, fmaxf(sv[j][0], sv[j][1]));
        m1 = fmaxf(m1, fmaxf(sv[j][2], sv[j][3]));
    }
    m0 = fmaxf(m0, __shfl_xor_sync(0xffffffffu, m0, 1));
    m0 = fmaxf(m0, __shfl_xor_sync(0xffffffffu, m0, 2));
    m1 = fmaxf(m1, __shfl_xor_sync(0xffffffffu, m1, 1));
    m1 = fmaxf(m1, __shfl_xor_sync(0xffffffffu, m1, 2));
    if ((lane & 3) == 0) {
        red[r0 * 8 + (wid & 3)] = m0;
        red[r1 * 8 + (wid & 3)] = m1;
    }
    __syncthreads();
    float mx0 = fmaxf(fmaxf(red[r0 * 8 + 0], red[r0 * 8 + 1]),
                      fmaxf(red[r0 * 8 + 2], red[r0 * 8 + 3]));
    float mx1 = fmaxf(fmaxf(red[r1 * 8 + 0], red[r1 * 8 + 1]),
                      fmaxf(red[r1 * 8 + 2], red[r1 * 8 + 3]));
    float e[3][4], sum0 = 0.f, sum1 = 0.f;
#pragma unroll
    for (int j = 0; j < 3; j++) {
        e[j][0] = __expf(sv[j][0] - mx0);
        e[j][1] = __expf(sv[j][1] - mx0);
        e[j][2] = __expf(sv[j][2] - mx1);
        e[j][3] = __expf(sv[j][3] - mx1);
        sum0 += e[j][0] + e[j][1];
        sum1 += e[j][2] + e[j][3];
    }
    sum0 += __shfl_xor_sync(0xffffffffu, sum0, 1);
    sum0 += __shfl_xor_sync(0xffffffffu, sum0, 2);
    sum1 += __shfl_xor_sync(0xffffffffu, sum1, 1);
    sum1 += __shfl_xor_sync(0xffffffffu, sum1, 2);
    if ((lane & 3) == 0) {
        red[r0 * 8 + 4 + (wid & 3)] = sum0;
        red[r1 * 8 + 4 + (wid & 3)] = sum1;
    }
    __syncthreads();
    float inv0 = 1.f / (red[r0 * 8 + 4] + red[r0 * 8 + 5] + red[r0 * 8 + 6] + red[r0 * 8 + 7]);
    float inv1 = 1.f / (red[r1 * 8 + 4] + red[r1 * 8 + 5] + red[r1 * 8 + 6] + red[r1 * 8 + 7]);

    // P -> smem hi/lo
#pragma unroll
    for (int j = 0; j < 3; j++) {
        int nb = (nfb + j) * 8 + (lane & 3) * 2;
        uint32_t h0, l0, h1, l1;
        split2h(e[j][0] * inv0, e[j][1] * inv0, h0, l0);
        split2h(e[j][2] * inv1, e[j][3] * inv1, h1, l1);
        *reinterpret_cast<uint32_t*>(sm + A_PH + r0 * VT_ROW + nb * 2) = h0;
        *reinterpret_cast<uint32_t*>(sm + A_PL + r0 * VT_ROW + nb * 2) = l0;
        *reinterpret_cast<uint32_t*>(sm + A_PH + r1 * VT_ROW + nb * 2) = h1;
        *reinterpret_cast<uint32_t*>(sm + A_PL + r1 * VT_ROW + nb * 2) = l1;
    }
    __syncthreads();

    // O = P*V
    const int nc = wid & 3;
    float oacc[4] = {0.f, 0.f, 0.f, 0.f};
#pragma unroll
    for (int kf = 0; kf < 6; kf++) {
        uint32_t ph[4], pl[4], vv[2];
        uint32_t poff = (uint32_t)((mf * 16 + lm_row) * VT_ROW) + kf * 32 + lm_chunk;
        LDM_X4(ph, sb + A_PH + poff);
        LDM_X4(pl, sb + A_PL + poff);
        uint32_t voff = (uint32_t)((nc * 8 + (lane & 7)) * VT_ROW) + kf * 32 +
                        (((lane >> 3) & 1) * 16);
        LDM_X2(vv, sb + A_VT + voff);
        MMA_F16(oacc, ph, vv);
        MMA_F16(oacc, pl, vv);
    }

    // gate by G, split hi/lo, store
    {
        int gcol = h * 32 + nc * 8 + (lane & 3) * 2;
        size_t e0 = (size_t)(b * S_ + s0 + r0) * 256 + gcol;
        size_t e1 = (size_t)(b * S_ + s0 + r1) * 256 + gcol;
        float2 gA = *reinterpret_cast<const float2*>(g_G + e0);
        float2 gB = *reinterpret_cast<const float2*>(g_G + e1);
        uint32_t h0, l0, h1, l1;
        split2h(oacc[0] * gA.x, oacc[1] * gA.y, h0, l0);
        split2h(oacc[2] * gB.x, oacc[3] * gB.y, h1, l1);
        *reinterpret_cast<uint32_t*>(g_Oh + e0) = h0;
        *reinterpret_cast<uint32_t*>(g_Ol + e0) = l0;
        *reinterpret_cast<uint32_t*>(g_Oh + e1) = h1;
        *reinterpret_cast<uint32_t*>(g_Ol + e1) = l1;
    }
}

// ============================================================
extern "C" void kernel_launch(void* const* d_in, const int* in_sizes, int n_in,
                              void* d_out, int out_size) {
    const float* Qin = (const float*)d_in[0];
    const float* Kin = (const float*)d_in[1];
    const float* Vin = (const float*)d_in[2];
    const float* QT  = (const float*)d_in[3];
    const float* KT  = (const float*)d_in[4];
    const float* VT  = (const float*)d_in[5];
    const float* GW  = (const float*)d_in[6];
    const float* Gb  = (const float*)d_in[7];
    const float* OW  = (const float*)d_in[8];
    const float* Ob  = (const float*)d_in[9];
    float* out = (float*)d_out;

    cudaFuncSetAttribute(proj_kernel, cudaFuncAttributeMaxDynamicSharedMemorySize, SMEM_PROJ);
    cudaFuncSetAttribute(out_kernel,  cudaFuncAttributeMaxDynamicSharedMemorySize, SMEM_OUT);

    prep_inputs<<<dim3(M_ * D_ / 1024, 3), 256>>>(Qin, Kin, Vin);
    prep_wstraight<<<dim3(64, 2), 256>>>(GW, OW);
    prep_wtrans<<<dim3(8, 8, 3), 256>>>(QT, KT, VT);

    proj_kernel<<<dim3(2, 32, 4), 256, SMEM_PROJ>>>(Gb);
    attn_kernel<<<dim3(S_ / 32, H_, B_), 256>>>();
    out_kernel<<<dim3(2, 64, 1), 256, SMEM_OUT>>>(Ob, out);
}

// round 6
// speedup vs baseline: 3.7153x; 1.1183x over previous
#include <cuda_runtime.h>
#include <cuda_fp16.h>
#include <math.h>
#include <stdint.h>

#define B_  2
#define S_  2048
#define D_  256
#define H_  8
#define C_  32
#define OUT_ 256
#define WIN_ 32
#define M_  (B_ * S_)

// -------- device scratch --------
__device__ __align__(16) __half g_Ah[3 * M_ * D_];
__device__ __align__(16) __half g_Al[3 * M_ * D_];
__device__ __align__(16) __half g_W [5 * 256 * 256]; // 0=QT^T 1=KT^T 2=VT^T 3=GW 4=OW ([n][k])
__device__ __align__(16) __half g_Qh[M_ * D_], g_Ql[M_ * D_];
__device__ __align__(16) __half g_K [M_ * D_];
__device__ __align__(16) __half g_V [M_ * D_];
__device__ __align__(16) float  g_G [M_ * D_];
__device__ __align__(16) __half g_Oh[M_ * D_], g_Ol[M_ * D_];

// ================= helpers =================
__device__ __forceinline__ uint32_t smem_u32(const void* p) {
    uint32_t a;
    asm("{ .reg .u64 t; cvta.to.shared.u64 t, %1; cvt.u32.u64 %0, t; }" : "=r"(a) : "l"(p));
    return a;
}
#define LDM_X4(r, addr) \
    asm volatile("ldmatrix.sync.aligned.m8n8.x4.shared.b16 {%0,%1,%2,%3}, [%4];" \
        : "=r"((r)[0]), "=r"((r)[1]), "=r"((r)[2]), "=r"((r)[3]) : "r"(addr))
#define LDM_X2(r, addr) \
    asm volatile("ldmatrix.sync.aligned.m8n8.x2.shared.b16 {%0,%1}, [%2];" \
        : "=r"((r)[0]), "=r"((r)[1]) : "r"(addr))
#define MMA_F16(c, a, b) \
    asm volatile("mma.sync.aligned.m16n8k16.row.col.f32.f16.f16.f32 " \
        "{%0,%1,%2,%3}, {%4,%5,%6,%7}, {%8,%9}, {%0,%1,%2,%3};" \
        : "+f"((c)[0]), "+f"((c)[1]), "+f"((c)[2]), "+f"((c)[3]) \
        : "r"((a)[0]), "r"((a)[1]), "r"((a)[2]), "r"((a)[3]), "r"((b)[0]), "r"((b)[1]))
#define CP_ASYNC16(dst, src) \
    asm volatile("cp.async.cg.shared.global [%0], [%1], 16;" :: "r"(dst), "l"(src))
#define CP_COMMIT() asm volatile("cp.async.commit_group;" ::: "memory")
#define CP_WAIT(n)  asm volatile("cp.async.wait_group %0;" :: "n"(n) : "memory")

__device__ __forceinline__ void split2h(float a, float b, uint32_t& h, uint32_t& l) {
    __half2 hi2 = __floats2half2_rn(a, b);
    float ra = a - __low2float(hi2);
    float rb = b - __high2float(hi2);
    __half2 lo2 = __floats2half2_rn(ra, rb);
    h = *reinterpret_cast<uint32_t*>(&hi2);
    l = *reinterpret_cast<uint32_t*>(&lo2);
}

// ================= fused prep kernel =================
// blocks [0, 3072): input split; [3072, 3200): GW/OW straight; [3200, 3392): QT/KT/VT transpose
__global__ void prep_all(const float* __restrict__ Qin, const float* __restrict__ Kin,
                         const float* __restrict__ Vin, const float* __restrict__ QT,
                         const float* __restrict__ KT,  const float* __restrict__ VT,
                         const float* __restrict__ GW,  const float* __restrict__ OW) {
    int blk = blockIdx.x;
    if (blk < 3072) {
        int z = blk >> 10;                 // 0..2
        int bx = blk & 1023;
        const float* src = (z == 0) ? Qin : (z == 1) ? Kin : Vin;
        size_t base = (size_t)z * (M_ * D_);
        int i = bx * 256 + threadIdx.x;
        float4 v = reinterpret_cast<const float4*>(src)[i];
        uint32_t h0, l0, h1, l1;
        split2h(v.x, v.y, h0, l0);
        split2h(v.z, v.w, h1, l1);
        reinterpret_cast<uint2*>(g_Ah + base)[i] = make_uint2(h0, h1);
        reinterpret_cast<uint2*>(g_Al + base)[i] = make_uint2(l0, l1);
    } else if (blk < 3200) {
        int t = blk - 3072;
        int z = t >> 6;                    // 0..1
        int bx = t & 63;
        const float* src = (z == 0) ? GW : OW;
        size_t base = (size_t)(3 + z) * 65536;
        int i = bx * 256 + threadIdx.x;
        float4 v = reinterpret_cast<const float4*>(src)[i];
        __half2 a = __floats2half2_rn(v.x, v.y);
        __half2 b = __floats2half2_rn(v.z, v.w);
        reinterpret_cast<uint2*>(g_W + base)[i] =
            make_uint2(*reinterpret_cast<uint32_t*>(&a), *reinterpret_cast<uint32_t*>(&b));
    } else {
        int t = blk - 3200;                // 0..191  (z*64 + ky*8 + nx)
        int z = t >> 6;
        int ky = (t >> 3) & 7;
        int nx = t & 7;
        const float* src = (z == 0) ? QT : (z == 1) ? KT : VT;
        size_t base = (size_t)z * 65536;
        __shared__ float tr[32][33];
        int tx = threadIdx.x & 31, ty = threadIdx.x >> 5;
        int k0 = ky * 32, n0 = nx * 32;
#pragma unroll
        for (int r = 0; r < 4; r++)
            tr[ty + r * 8][tx] = src[(size_t)(k0 + ty + r * 8) * 256 + n0 + tx];
        __syncthreads();
#pragma unroll
        for (int r = 0; r < 4; r++) {
            int n = n0 + ty + r * 8, k = k0 + tx;
            g_W[base + (size_t)n * 256 + k] = __float2half(tr[tx][ty + r * 8]);
        }
    }
}

// ================= fp16 MMA GEMM: BM=64, BN=128, 3-stage pipeline =================
#define G_ROW  80
#define BM_    64
#define STAGE_ ((2 * BM_ + 128) * G_ROW)   // 20480
#define SMEM_GEMM (3 * STAGE_)             // 61440

// MODE: 0 = split half out, 1 = f32+bias+sigmoid, 2 = f32+bias, 3 = single half out
template <int MODE>
__device__ __forceinline__ void gemm_core(const __half* __restrict__ Ah, const __half* __restrict__ Al,
                                          const __half* __restrict__ Bn,
                                          const float* __restrict__ bias,
                                          float* __restrict__ Yf,
                                          __half* __restrict__ Yh, __half* __restrict__ Yl) {
    extern __shared__ char smem[];
    const uint32_t sb = smem_u32(smem);
    const int tid = threadIdx.x, wid = tid >> 5, lane = tid & 31;
    const int warp_m = wid & 1;         // 2 warps along M
    const int warp_n = wid >> 1;        // 4 warps along N
    const int m0 = blockIdx.y * BM_, n0 = blockIdx.x * 128;
    const int lm_row = lane & 15, lm_chunk = (lane >> 4) * 16;

    float acc[2][4][4];
#pragma unroll
    for (int i = 0; i < 2; i++)
#pragma unroll
        for (int j = 0; j < 4; j++)
#pragma unroll
            for (int q = 0; q < 4; q++) acc[i][j][q] = 0.f;

    auto stage = [&](int kc, int buf) {
#pragma unroll
        for (int task = tid; task < 1024; task += 256) {
            const __half* s;
            uint32_t dbase;
            int row = (task & 255) >> 2, ch = task & 3;
            if (task < 256) {
                s = Ah + (size_t)(m0 + row) * 256 + kc * 32 + ch * 8;
                dbase = 0;
            } else if (task < 512) {
                s = Al + (size_t)(m0 + row) * 256 + kc * 32 + ch * 8;
                dbase = BM_ * G_ROW;
            } else {
                row = (task - 512) >> 2;
                s = Bn + (size_t)(n0 + row) * 256 + kc * 32 + ch * 8;
                dbase = 2 * BM_ * G_ROW;
            }
            CP_ASYNC16(sb + buf * STAGE_ + dbase + row * G_ROW + ch * 16, s);
        }
    };

    stage(0, 0); CP_COMMIT();
    stage(1, 1); CP_COMMIT();

    for (int kc = 0; kc < 8; kc++) {
        if (kc < 7) CP_WAIT(1); else CP_WAIT(0);
        __syncthreads();

        const uint32_t bb = sb + (kc % 3) * STAGE_;
#pragma unroll
        for (int ks = 0; ks < 2; ks++) {
            const uint32_t kbyte = ks * 32 + lm_chunk;
            uint32_t ah[2][4], al[2][4], bfr[4][2];
#pragma unroll
            for (int mf = 0; mf < 2; mf++) {
                uint32_t off = (uint32_t)((warp_m * 32 + mf * 16 + lm_row) * G_ROW) + kbyte;
                LDM_X4(ah[mf], bb + off);
                LDM_X4(al[mf], bb + BM_ * G_ROW + off);
            }
#pragma unroll
            for (int np = 0; np < 2; np++) {
                uint32_t off = (uint32_t)((warp_n * 32 + np * 16 + lm_row) * G_ROW) + kbyte;
                uint32_t th[4];
                LDM_X4(th, bb + 2 * BM_ * G_ROW + off);
                bfr[np * 2][0] = th[0]; bfr[np * 2][1] = th[2];
                bfr[np * 2 + 1][0] = th[1]; bfr[np * 2 + 1][1] = th[3];
            }
#pragma unroll
            for (int mf = 0; mf < 2; mf++)
#pragma unroll
                for (int nf = 0; nf < 4; nf++) {
                    MMA_F16(acc[mf][nf], ah[mf], bfr[nf]);
                    MMA_F16(acc[mf][nf], al[mf], bfr[nf]);
                }
        }

        if (kc + 2 < 8) { stage(kc + 2, (kc + 2) % 3); CP_COMMIT(); }
    }

    // epilogue
#pragma unroll
    for (int mf = 0; mf < 2; mf++) {
        int row = m0 + warp_m * 32 + mf * 16 + (lane >> 2);
#pragma unroll
        for (int nf = 0; nf < 4; nf++) {
            int col = n0 + warp_n * 32 + nf * 8 + (lane & 3) * 2;
            float v0 = acc[mf][nf][0], v1 = acc[mf][nf][1];
            float v2 = acc[mf][nf][2], v3 = acc[mf][nf][3];
            if (MODE == 1 || MODE == 2) {
                float b0 = bias[col], b1 = bias[col + 1];
                v0 += b0; v1 += b1; v2 += b0; v3 += b1;
                if (MODE == 1) {
                    v0 = 1.f / (1.f + __expf(-v0));
                    v1 = 1.f / (1.f + __expf(-v1));
                    v2 = 1.f / (1.f + __expf(-v2));
                    v3 = 1.f / (1.f + __expf(-v3));
                }
                *reinterpret_cast<float2*>(Yf + (size_t)row * 256 + col)       = make_float2(v0, v1);
                *reinterpret_cast<float2*>(Yf + (size_t)(row + 8) * 256 + col) = make_float2(v2, v3);
            } else if (MODE == 0) {
                uint32_t h0, l0, h1, l1;
                split2h(v0, v1, h0, l0);
                split2h(v2, v3, h1, l1);
                *reinterpret_cast<uint32_t*>(Yh + (size_t)row * 256 + col)       = h0;
                *reinterpret_cast<uint32_t*>(Yl + (size_t)row * 256 + col)       = l0;
                *reinterpret_cast<uint32_t*>(Yh + (size_t)(row + 8) * 256 + col) = h1;
                *reinterpret_cast<uint32_t*>(Yl + (size_t)(row + 8) * 256 + col) = l1;
            } else {
                __half2 a = __floats2half2_rn(v0, v1);
                __half2 b = __floats2half2_rn(v2, v3);
                *reinterpret_cast<uint32_t*>(Yh + (size_t)row * 256 + col)       = *reinterpret_cast<uint32_t*>(&a);
                *reinterpret_cast<uint32_t*>(Yh + (size_t)(row + 8) * 256 + col) = *reinterpret_cast<uint32_t*>(&b);
            }
        }
    }
}

__global__ void __launch_bounds__(256, 3)
proj_kernel(const float* __restrict__ Gb) {
    int z = blockIdx.z;
    int xslot = (z == 3) ? 2 : z;
    const __half* Ah = g_Ah + (size_t)xslot * (M_ * D_);
    const __half* Al = g_Al + (size_t)xslot * (M_ * D_);
    const __half* Bn = g_W + (size_t)z * 65536;
    if (z == 0)      gemm_core<0>(Ah, Al, Bn, nullptr, nullptr, g_Qh, g_Ql);
    else if (z == 1) gemm_core<3>(Ah, Al, Bn, nullptr, nullptr, g_K, nullptr);
    else if (z == 2) gemm_core<3>(Ah, Al, Bn, nullptr, nullptr, g_V, nullptr);
    else             gemm_core<1>(Ah, Al, Bn, Gb, g_G, nullptr, nullptr);
}

__global__ void __launch_bounds__(256, 3)
out_kernel(const float* __restrict__ Ob, float* __restrict__ out) {
    gemm_core<2>(g_Oh, g_Ol, g_W + 4 * 65536, Ob, out, nullptr, nullptr);
}

// ================= fp16 tensor-core local-window attention =================
#define A_QH 0
#define A_QL 2560
#define A_K  5120
#define A_VT 12800
#define A_PH 19456
#define A_PL 26112
#define A_RED 32768
#define A_TOTAL 33792
#define QK_ROW 80
#define VT_ROW 208

__global__ void __launch_bounds__(256)
attn_kernel() {
    __shared__ __align__(16) char sm[A_TOTAL];
    const uint32_t sb = smem_u32(sm);
    float* red = reinterpret_cast<float*>(sm + A_RED);

    const int b = blockIdx.z, h = blockIdx.y, s0 = blockIdx.x * 32;
    const int tid = threadIdx.x, wid = tid >> 5, lane = tid & 31;
    const int lm_row = lane & 15, lm_chunk = (lane >> 4) * 16;

    for (int i = tid; i < 384; i += 256) {
        int row = i >> 2, ch = i & 3;
        int t = s0 - 32 + row;
        uint4 v = make_uint4(0, 0, 0, 0);
        if (t >= 0 && t < S_)
            v = *reinterpret_cast<const uint4*>(g_K + (size_t)(b * S_ + t) * 256 + h * 32 + ch * 8);
        *reinterpret_cast<uint4*>(sm + A_K + row * QK_ROW + ch * 16) = v;
    }
    for (int i = tid; i < 128; i += 256) {
        int row = i >> 2, ch = i & 3;
        size_t e = (size_t)(b * S_ + s0 + row) * 256 + h * 32 + ch * 8;
        *reinterpret_cast<uint4*>(sm + A_QH + row * QK_ROW + ch * 16) =
            *reinterpret_cast<const uint4*>(g_Qh + e);
        *reinterpret_cast<uint4*>(sm + A_QL + row * QK_ROW + ch * 16) =
            *reinterpret_cast<const uint4*>(g_Ql + e);
    }
    for (int i = tid; i < 3072; i += 256) {
        int trel = i >> 5, c = i & 31;
        int t = s0 - 32 + trel;
        __half v = __float2half(0.f);
        if (t >= 0 && t < S_) v = g_V[(size_t)(b * S_ + t) * 256 + h * 32 + c];
        *reinterpret_cast<__half*>(sm + A_VT + c * VT_ROW + trel * 2) = v;
    }
    __syncthreads();

    const int mf = wid >> 2;
    const int nfb = (wid & 3) * 3;
    float sc[3][4];
#pragma unroll
    for (int j = 0; j < 3; j++)
#pragma unroll
        for (int q = 0; q < 4; q++) sc[j][q] = 0.f;

#pragma unroll
    for (int kf = 0; kf < 2; kf++) {
        uint32_t qh[4], ql[4];
        uint32_t aoff = (uint32_t)((mf * 16 + lm_row) * QK_ROW) + kf * 32 + lm_chunk;
        LDM_X4(qh, sb + A_QH + aoff);
        LDM_X4(ql, sb + A_QL + aoff);
#pragma unroll
        for (int j = 0; j < 3; j++) {
            uint32_t kk[2];
            uint32_t boff = (uint32_t)(((nfb + j) * 8 + (lane & 7)) * QK_ROW) + kf * 32 +
                            (((lane >> 3) & 1) * 16);
            LDM_X2(kk, sb + A_K + boff);
            MMA_F16(sc[j], qh, kk);
            MMA_F16(sc[j], ql, kk);
        }
    }

    const float rsC = 0.17677669529663689f;
    const int r0 = mf * 16 + (lane >> 2);
    const int r1 = r0 + 8;
    float sv[3][4];
#pragma unroll
    for (int j = 0; j < 3; j++) {
        int nb = (nfb + j) * 8 + (lane & 3) * 2;
#pragma unroll
        for (int q = 0; q < 4; q++) {
            int n = nb + (q & 1);
            int row = (q < 2) ? r0 : r1;
            int t = s0 - 32 + n;
            bool ok = (n >= row) && (n <= row + 64) && (t >= 0) && (t < S_);
            sv[j][q] = ok ? sc[j][q] * rsC : -1e30f;
        }
    }
    float m0 = -1e30f, m1 = -1e30f;
#pragma unroll
    for (int j = 0; j < 3; j++) {
        m0 = fmaxf(m0, fmaxf(sv[j][0], sv[j][1]));
        m1 = fmaxf(m1, fmaxf(sv[j][2], sv[j][3]));
    }
    m0 = fmaxf(m0, __shfl_xor_sync(0xffffffffu, m0, 1));
    m0 = fmaxf(m0, __shfl_xor_sync(0xffffffffu, m0, 2));
    m1 = fmaxf(m1, __shfl_xor_sync(0xffffffffu, m1, 1));
    m1 = fmaxf(m1, __shfl_xor_sync(0xffffffffu, m1, 2));
    if ((lane & 3) == 0) {
        red[r0 * 8 + (wid & 3)] = m0;
        red[r1 * 8 + (wid & 3)] = m1;
    }
    __syncthreads();
    float mx0 = fmaxf(fmaxf(red[r0 * 8 + 0], red[r0 * 8 + 1]),
                      fmaxf(red[r0 * 8 + 2], red[r0 * 8 + 3]));
    float mx1 = fmaxf(fmaxf(red[r1 * 8 + 0], red[r1 * 8 + 1]),
                      fmaxf(red[r1 * 8 + 2], red[r1 * 8 + 3]));
    float e[3][4], sum0 = 0.f, sum1 = 0.f;
#pragma unroll
    for (int j = 0; j < 3; j++) {
        e[j][0] = __expf(sv[j][0] - mx0);
        e[j][1] = __expf(sv[j][1] - mx0);
        e[j][2] = __expf(sv[j][2] - mx1);
        e[j][3] = __expf(sv[j][3] - mx1);
        sum0 += e[j][0] + e[j][1];
        sum1 += e[j][2] + e[j][3];
    }
    sum0 += __shfl_xor_sync(0xffffffffu, sum0, 1);
    sum0 += __shfl_xor_sync(0xffffffffu, sum0, 2);
    sum1 += __shfl_xor_sync(0xffffffffu, sum1, 1);
    sum1 += __shfl_xor_sync(0xffffffffu, sum1, 2);
    if ((lane & 3) == 0) {
        red[r0 * 8 + 4 + (wid & 3)] = sum0;
        red[r1 * 8 + 4 + (wid & 3)] = sum1;
    }
    __syncthreads();
    float inv0 = 1.f / (red[r0 * 8 + 4] + red[r0 * 8 + 5] + red[r0 * 8 + 6] + red[r0 * 8 + 7]);
    float inv1 = 1.f / (red[r1 * 8 + 4] + red[r1 * 8 + 5] + red[r1 * 8 + 6] + red[r1 * 8 + 7]);

#pragma unroll
    for (int j = 0; j < 3; j++) {
        int nb = (nfb + j) * 8 + (lane & 3) * 2;
        uint32_t h0, l0, h1, l1;
        split2h(e[j][0] * inv0, e[j][1] * inv0, h0, l0);
        split2h(e[j][2] * inv1, e[j][3] * inv1, h1, l1);
        *reinterpret_cast<uint32_t*>(sm + A_PH + r0 * VT_ROW + nb * 2) = h0;
        *reinterpret_cast<uint32_t*>(sm + A_PL + r0 * VT_ROW + nb * 2) = l0;
        *reinterpret_cast<uint32_t*>(sm + A_PH + r1 * VT_ROW + nb * 2) = h1;
        *reinterpret_cast<uint32_t*>(sm + A_PL + r1 * VT_ROW + nb * 2) = l1;
    }
    __syncthreads();

    const int nc = wid & 3;
    float oacc[4] = {0.f, 0.f, 0.f, 0.f};
#pragma unroll
    for (int kf = 0; kf < 6; kf++) {
        uint32_t ph[4], pl[4], vv[2];
        uint32_t poff = (uint32_t)((mf * 16 + lm_row) * VT_ROW) + kf * 32 + lm_chunk;
        LDM_X4(ph, sb + A_PH + poff);
        LDM_X4(pl, sb + A_PL + poff);
        uint32_t voff = (uint32_t)((nc * 8 + (lane & 7)) * VT_ROW) + kf * 32 +
                        (((lane >> 3) & 1) * 16);
        LDM_X2(vv, sb + A_VT + voff);
        MMA_F16(oacc, ph, vv);
        MMA_F16(oacc, pl, vv);
    }

    {
        int gcol = h * 32 + nc * 8 + (lane & 3) * 2;
        size_t e0 = (size_t)(b * S_ + s0 + r0) * 256 + gcol;
        size_t e1 = (size_t)(b * S_ + s0 + r1) * 256 + gcol;
        float2 gA = *reinterpret_cast<const float2*>(g_G + e0);
        float2 gB = *reinterpret_cast<const float2*>(g_G + e1);
        uint32_t h0, l0, h1, l1;
        split2h(oacc[0] * gA.x, oacc[1] * gA.y, h0, l0);
        split2h(oacc[2] * gB.x, oacc[3] * gB.y, h1, l1);
        *reinterpret_cast<uint32_t*>(g_Oh + e0) = h0;
        *reinterpret_cast<uint32_t*>(g_Ol + e0) = l0;
        *reinterpret_cast<uint32_t*>(g_Oh + e1) = h1;
        *reinterpret_cast<uint32_t*>(g_Ol + e1) = l1;
    }
}

// ============================================================
extern "C" void kernel_launch(void* const* d_in, const int* in_sizes, int n_in,
                              void* d_out, int out_size) {
    const float* Qin = (const float*)d_in[0];
    const float* Kin = (const float*)d_in[1];
    const float* Vin = (const float*)d_in[2];
    const float* QT  = (const float*)d_in[3];
    const float* KT  = (const float*)d_in[4];
    const float* VT  = (const float*)d_in[5];
    const float* GW  = (const float*)d_in[6];
    const float* Gb  = (const float*)d_in[7];
    const float* OW  = (const float*)d_in[8];
    const float* Ob  = (const float*)d_in[9];
    float* out = (float*)d_out;

    cudaFuncSetAttribute(proj_kernel, cudaFuncAttributeMaxDynamicSharedMemorySize, SMEM_GEMM);
    cudaFuncSetAttribute(out_kernel,  cudaFuncAttributeMaxDynamicSharedMemorySize, SMEM_GEMM);

    prep_all<<<3392, 256>>>(Qin, Kin, Vin, QT, KT, VT, GW, OW);
    proj_kernel<<<dim3(2, 64, 4), 256, SMEM_GEMM>>>(Gb);
    attn_kernel<<<dim3(S_ / 32, H_, B_), 256>>>();
    out_kernel<<<dim3(2, 64, 1), 256, SMEM_GEMM>>>(Ob, out);
}

// round 7
// speedup vs baseline: 4.1358x; 1.1132x over previous
#include <cuda_runtime.h>
#include <cuda_fp16.h>
#include <math.h>
#include <stdint.h>

#define B_  2
#define S_  2048
#define D_  256
#define H_  8
#define C_  32
#define OUT_ 256
#define WIN_ 32
#define M_  (B_ * S_)

// -------- device scratch --------
__device__ __align__(16) __half g_Ah[3 * M_ * D_];
__device__ __align__(16) __half g_Al[3 * M_ * D_];
__device__ __align__(16) __half g_W [5 * 256 * 256]; // 0=QT^T 1=KT^T 2=VT^T 3=GW 4=OW ([n][k])
__device__ __align__(16) __half g_Qh[M_ * D_], g_Ql[M_ * D_];
__device__ __align__(16) __half g_K [M_ * D_];
__device__ __align__(16) __half g_V [M_ * D_];
__device__ __align__(16) float  g_G [M_ * D_];
__device__ __align__(16) __half g_Oh[M_ * D_], g_Ol[M_ * D_];

// ================= helpers =================
__device__ __forceinline__ uint32_t smem_u32(const void* p) {
    uint32_t a;
    asm("{ .reg .u64 t; cvta.to.shared.u64 t, %1; cvt.u32.u64 %0, t; }" : "=r"(a) : "l"(p));
    return a;
}
#define LDM_X4(r, addr) \
    asm volatile("ldmatrix.sync.aligned.m8n8.x4.shared.b16 {%0,%1,%2,%3}, [%4];" \
        : "=r"((r)[0]), "=r"((r)[1]), "=r"((r)[2]), "=r"((r)[3]) : "r"(addr))
#define LDM_X2(r, addr) \
    asm volatile("ldmatrix.sync.aligned.m8n8.x2.shared.b16 {%0,%1}, [%2];" \
        : "=r"((r)[0]), "=r"((r)[1]) : "r"(addr))
#define LDM_X2_T(r, addr) \
    asm volatile("ldmatrix.sync.aligned.m8n8.x2.trans.shared.b16 {%0,%1}, [%2];" \
        : "=r"((r)[0]), "=r"((r)[1]) : "r"(addr))
#define MMA_F16(c, a, b) \
    asm volatile("mma.sync.aligned.m16n8k16.row.col.f32.f16.f16.f32 " \
        "{%0,%1,%2,%3}, {%4,%5,%6,%7}, {%8,%9}, {%0,%1,%2,%3};" \
        : "+f"((c)[0]), "+f"((c)[1]), "+f"((c)[2]), "+f"((c)[3]) \
        : "r"((a)[0]), "r"((a)[1]), "r"((a)[2]), "r"((a)[3]), "r"((b)[0]), "r"((b)[1]))
#define CP_ASYNC16(dst, src) \
    asm volatile("cp.async.cg.shared.global [%0], [%1], 16;" :: "r"(dst), "l"(src))
#define CP_COMMIT() asm volatile("cp.async.commit_group;" ::: "memory")
#define CP_WAIT(n)  asm volatile("cp.async.wait_group %0;" :: "n"(n) : "memory")

__device__ __forceinline__ void split2h(float a, float b, uint32_t& h, uint32_t& l) {
    __half2 hi2 = __floats2half2_rn(a, b);
    float ra = a - __low2float(hi2);
    float rb = b - __high2float(hi2);
    __half2 lo2 = __floats2half2_rn(ra, rb);
    h = *reinterpret_cast<uint32_t*>(&hi2);
    l = *reinterpret_cast<uint32_t*>(&lo2);
}

// ================= fused prep kernel =================
__global__ void prep_all(const float* __restrict__ Qin, const float* __restrict__ Kin,
                         const float* __restrict__ Vin, const float* __restrict__ QT,
                         const float* __restrict__ KT,  const float* __restrict__ VT,
                         const float* __restrict__ GW,  const float* __restrict__ OW) {
    int blk = blockIdx.x;
    if (blk < 3072) {
        int z = blk >> 10;
        int bx = blk & 1023;
        const float* src = (z == 0) ? Qin : (z == 1) ? Kin : Vin;
        size_t base = (size_t)z * (M_ * D_);
        int i = bx * 256 + threadIdx.x;
        float4 v = reinterpret_cast<const float4*>(src)[i];
        uint32_t h0, l0, h1, l1;
        split2h(v.x, v.y, h0, l0);
        split2h(v.z, v.w, h1, l1);
        reinterpret_cast<uint2*>(g_Ah + base)[i] = make_uint2(h0, h1);
        reinterpret_cast<uint2*>(g_Al + base)[i] = make_uint2(l0, l1);
    } else if (blk < 3200) {
        int t = blk - 3072;
        int z = t >> 6;
        int bx = t & 63;
        const float* src = (z == 0) ? GW : OW;
        size_t base = (size_t)(3 + z) * 65536;
        int i = bx * 256 + threadIdx.x;
        float4 v = reinterpret_cast<const float4*>(src)[i];
        __half2 a = __floats2half2_rn(v.x, v.y);
        __half2 b = __floats2half2_rn(v.z, v.w);
        reinterpret_cast<uint2*>(g_W + base)[i] =
            make_uint2(*reinterpret_cast<uint32_t*>(&a), *reinterpret_cast<uint32_t*>(&b));
    } else {
        int t = blk - 3200;
        int z = t >> 6;
        int ky = (t >> 3) & 7;
        int nx = t & 7;
        const float* src = (z == 0) ? QT : (z == 1) ? KT : VT;
        size_t base = (size_t)z * 65536;
        __shared__ float tr[32][33];
        int tx = threadIdx.x & 31, ty = threadIdx.x >> 5;
        int k0 = ky * 32, n0 = nx * 32;
#pragma unroll
        for (int r = 0; r < 4; r++)
            tr[ty + r * 8][tx] = src[(size_t)(k0 + ty + r * 8) * 256 + n0 + tx];
        __syncthreads();
#pragma unroll
        for (int r = 0; r < 4; r++) {
            int n = n0 + ty + r * 8, k = k0 + tx;
            g_W[base + (size_t)n * 256 + k] = __float2half(tr[tx][ty + r * 8]);
        }
    }
}

// ================= fp16 MMA GEMM, templated tile =================
#define G_ROW  80
// MODE: 0 = split half out, 1 = f32+bias+sigmoid, 2 = f32+bias, 3 = single half out
template <int MODE, int BM, int BN>
__device__ __forceinline__ void gemm_core(const __half* __restrict__ Ah, const __half* __restrict__ Al,
                                          const __half* __restrict__ Bn,
                                          const float* __restrict__ bias,
                                          float* __restrict__ Yf,
                                          __half* __restrict__ Yh, __half* __restrict__ Yl) {
    extern __shared__ char smem[];
    const uint32_t sb = smem_u32(smem);
    const int tid = threadIdx.x, wid = tid >> 5, lane = tid & 31;

    constexpr int WM = BM / 32;                 // warps along M
    constexpr int WN = 8 / WM;                  // warps along N
    constexpr int NF = BN / (8 * WN);           // 8-wide n-frags per warp
    constexpr int ACH = BM * 4;                 // 16B chunks per A tile
    constexpr int TASKS = (2 * BM + BN) * 4;
    constexpr int STAGE = (2 * BM + BN) * G_ROW;

    const int warp_m = wid % WM, warp_n = wid / WM;
    const int m0 = blockIdx.y * BM, n0 = blockIdx.x * BN;
    const int lm_row = lane & 15, lm_chunk = (lane >> 4) * 16;

    float acc[2][NF][4];
#pragma unroll
    for (int i = 0; i < 2; i++)
#pragma unroll
        for (int j = 0; j < NF; j++)
#pragma unroll
            for (int q = 0; q < 4; q++) acc[i][j][q] = 0.f;

    auto stage = [&](int kc, int buf) {
#pragma unroll
        for (int task = tid; task < TASKS; task += 256) {
            const __half* s;
            uint32_t dbase;
            int row, ch = task & 3;
            if (task < ACH) {
                row = task >> 2;
                s = Ah + (size_t)(m0 + row) * 256 + kc * 32 + ch * 8;
                dbase = 0;
            } else if (task < 2 * ACH) {
                row = (task - ACH) >> 2;
                s = Al + (size_t)(m0 + row) * 256 + kc * 32 + ch * 8;
                dbase = BM * G_ROW;
            } else {
                row = (task - 2 * ACH) >> 2;
                s = Bn + (size_t)(n0 + row) * 256 + kc * 32 + ch * 8;
                dbase = 2 * BM * G_ROW;
            }
            CP_ASYNC16(sb + buf * STAGE + dbase + row * G_ROW + ch * 16, s);
        }
    };

    stage(0, 0); CP_COMMIT();
    stage(1, 1); CP_COMMIT();

    for (int kc = 0; kc < 8; kc++) {
        if (kc < 7) CP_WAIT(1); else CP_WAIT(0);
        __syncthreads();

        const uint32_t bb = sb + (kc % 3) * STAGE;
#pragma unroll
        for (int ks = 0; ks < 2; ks++) {
            const uint32_t kbyte = ks * 32 + lm_chunk;
            uint32_t ah[2][4], al[2][4], bfr[NF][2];
#pragma unroll
            for (int mf = 0; mf < 2; mf++) {
                uint32_t off = (uint32_t)((warp_m * 32 + mf * 16 + lm_row) * G_ROW) + kbyte;
                LDM_X4(ah[mf], bb + off);
                LDM_X4(al[mf], bb + BM * G_ROW + off);
            }
#pragma unroll
            for (int np = 0; np < NF / 2; np++) {
                uint32_t off = (uint32_t)((warp_n * (NF * 8) + np * 16 + lm_row) * G_ROW) + kbyte;
                uint32_t th[4];
                LDM_X4(th, bb + 2 * BM * G_ROW + off);
                bfr[np * 2][0] = th[0]; bfr[np * 2][1] = th[2];
                bfr[np * 2 + 1][0] = th[1]; bfr[np * 2 + 1][1] = th[3];
            }
#pragma unroll
            for (int mf = 0; mf < 2; mf++)
#pragma unroll
                for (int nf = 0; nf < NF; nf++) {
                    MMA_F16(acc[mf][nf], ah[mf], bfr[nf]);
                    MMA_F16(acc[mf][nf], al[mf], bfr[nf]);
                }
        }

        if (kc + 2 < 8) { stage(kc + 2, (kc + 2) % 3); CP_COMMIT(); }
    }

    // epilogue
#pragma unroll
    for (int mf = 0; mf < 2; mf++) {
        int row = m0 + warp_m * 32 + mf * 16 + (lane >> 2);
#pragma unroll
        for (int nf = 0; nf < NF; nf++) {
            int col = n0 + warp_n * (NF * 8) + nf * 8 + (lane & 3) * 2;
            float v0 = acc[mf][nf][0], v1 = acc[mf][nf][1];
            float v2 = acc[mf][nf][2], v3 = acc[mf][nf][3];
            if (MODE == 1 || MODE == 2) {
                float b0 = bias[col], b1 = bias[col + 1];
                v0 += b0; v1 += b1; v2 += b0; v3 += b1;
                if (MODE == 1) {
                    v0 = 1.f / (1.f + __expf(-v0));
                    v1 = 1.f / (1.f + __expf(-v1));
                    v2 = 1.f / (1.f + __expf(-v2));
                    v3 = 1.f / (1.f + __expf(-v3));
                }
                *reinterpret_cast<float2*>(Yf + (size_t)row * 256 + col)       = make_float2(v0, v1);
                *reinterpret_cast<float2*>(Yf + (size_t)(row + 8) * 256 + col) = make_float2(v2, v3);
            } else if (MODE == 0) {
                uint32_t h0, l0, h1, l1;
                split2h(v0, v1, h0, l0);
                split2h(v2, v3, h1, l1);
                *reinterpret_cast<uint32_t*>(Yh + (size_t)row * 256 + col)       = h0;
                *reinterpret_cast<uint32_t*>(Yl + (size_t)row * 256 + col)       = l0;
                *reinterpret_cast<uint32_t*>(Yh + (size_t)(row + 8) * 256 + col) = h1;
                *reinterpret_cast<uint32_t*>(Yl + (size_t)(row + 8) * 256 + col) = l1;
            } else {
                __half2 a = __floats2half2_rn(v0, v1);
                __half2 b = __floats2half2_rn(v2, v3);
                *reinterpret_cast<uint32_t*>(Yh + (size_t)row * 256 + col)       = *reinterpret_cast<uint32_t*>(&a);
                *reinterpret_cast<uint32_t*>(Yh + (size_t)(row + 8) * 256 + col) = *reinterpret_cast<uint32_t*>(&b);
            }
        }
    }
}

#define SMEM_PROJ (3 * (2 * 64 + 128) * G_ROW)   // 61440
#define SMEM_OUT  (3 * (2 * 64 + 64) * G_ROW)    // 46080

__global__ void __launch_bounds__(256, 3)
proj_kernel(const float* __restrict__ Gb) {
    int z = blockIdx.z;
    int xslot = (z == 3) ? 2 : z;
    const __half* Ah = g_Ah + (size_t)xslot * (M_ * D_);
    const __half* Al = g_Al + (size_t)xslot * (M_ * D_);
    const __half* Bn = g_W + (size_t)z * 65536;
    if (z == 0)      gemm_core<0, 64, 128>(Ah, Al, Bn, nullptr, nullptr, g_Qh, g_Ql);
    else if (z == 1) gemm_core<3, 64, 128>(Ah, Al, Bn, nullptr, nullptr, g_K, nullptr);
    else if (z == 2) gemm_core<3, 64, 128>(Ah, Al, Bn, nullptr, nullptr, g_V, nullptr);
    else             gemm_core<1, 64, 128>(Ah, Al, Bn, Gb, g_G, nullptr, nullptr);
}

__global__ void __launch_bounds__(256, 4)
out_kernel(const float* __restrict__ Ob, float* __restrict__ out) {
    gemm_core<2, 64, 64>(g_Oh, g_Ol, g_W + 4 * 65536, Ob, out, nullptr, nullptr);
}

// ================= fp16 tensor-core local-window attention =================
#define A_QH 0
#define A_QL 2560
#define A_K  5120
#define A_V  12800
#define A_PH 20480
#define A_PL 27136
#define A_RED 33792
#define A_TOTAL 34816
#define QK_ROW 80
#define VT_ROW 208

__global__ void __launch_bounds__(256)
attn_kernel() {
    __shared__ __align__(16) char sm[A_TOTAL];
    const uint32_t sb = smem_u32(sm);
    float* red = reinterpret_cast<float*>(sm + A_RED);

    const int b = blockIdx.z, h = blockIdx.y, s0 = blockIdx.x * 32;
    const int tid = threadIdx.x, wid = tid >> 5, lane = tid & 31;
    const int lm_row = lane & 15, lm_chunk = (lane >> 4) * 16;

    // stage K and V (96 x 32) vectorized, natural [t][c] layout
    for (int i = tid; i < 384; i += 256) {
        int row = i >> 2, ch = i & 3;
        int t = s0 - 32 + row;
        uint4 vk = make_uint4(0, 0, 0, 0), vv = vk;
        if (t >= 0 && t < S_) {
            size_t e = (size_t)(b * S_ + t) * 256 + h * 32 + ch * 8;
            vk = *reinterpret_cast<const uint4*>(g_K + e);
            vv = *reinterpret_cast<const uint4*>(g_V + e);
        }
        *reinterpret_cast<uint4*>(sm + A_K + row * QK_ROW + ch * 16) = vk;
        *reinterpret_cast<uint4*>(sm + A_V + row * QK_ROW + ch * 16) = vv;
    }
    // stage Q (32 x 32) hi/lo
    for (int i = tid; i < 128; i += 256) {
        int row = i >> 2, ch = i & 3;
        size_t e = (size_t)(b * S_ + s0 + row) * 256 + h * 32 + ch * 8;
        *reinterpret_cast<uint4*>(sm + A_QH + row * QK_ROW + ch * 16) =
            *reinterpret_cast<const uint4*>(g_Qh + e);
        *reinterpret_cast<uint4*>(sm + A_QL + row * QK_ROW + ch * 16) =
            *reinterpret_cast<const uint4*>(g_Ql + e);
    }
    __syncthreads();

    // S = Q*K^T
    const int mf = wid >> 2;
    const int nfb = (wid & 3) * 3;
    float sc[3][4];
#pragma unroll
    for (int j = 0; j < 3; j++)
#pragma unroll
        for (int q = 0; q < 4; q++) sc[j][q] = 0.f;

#pragma unroll
    for (int kf = 0; kf < 2; kf++) {
        uint32_t qh[4], ql[4];
        uint32_t aoff = (uint32_t)((mf * 16 + lm_row) * QK_ROW) + kf * 32 + lm_chunk;
        LDM_X4(qh, sb + A_QH + aoff);
        LDM_X4(ql, sb + A_QL + aoff);
#pragma unroll
        for (int j = 0; j < 3; j++) {
            uint32_t kk[2];
            uint32_t boff = (uint32_t)(((nfb + j) * 8 + (lane & 7)) * QK_ROW) + kf * 32 +
                            (((lane >> 3) & 1) * 16);
            LDM_X2(kk, sb + A_K + boff);
            MMA_F16(sc[j], qh, kk);
            MMA_F16(sc[j], ql, kk);
        }
    }

    // mask + softmax
    const float rsC = 0.17677669529663689f;
    const int r0 = mf * 16 + (lane >> 2);
    const int r1 = r0 + 8;
    float sv[3][4];
#pragma unroll
    for (int j = 0; j < 3; j++) {
        int nb = (nfb + j) * 8 + (lane & 3) * 2;
#pragma unroll
        for (int q = 0; q < 4; q++) {
            int n = nb + (q & 1);
            int row = (q < 2) ? r0 : r1;
            int t = s0 - 32 + n;
            bool ok = (n >= row) && (n <= row + 64) && (t >= 0) && (t < S_);
            sv[j][q] = ok ? sc[j][q] * rsC : -1e30f;
        }
    }
    float m0 = -1e30f, m1 = -1e30f;
#pragma unroll
    for (int j = 0; j < 3; j++) {
        m0 = fmaxf(m0, fmaxf(sv[j][0], sv[j][1]));
        m1 = fmaxf(m1, fmaxf(sv[j][2], sv[j][3]));
    }
    m0 = fmaxf(m0, __shfl_xor_sync(0xffffffffu, m0, 1));
    m0 = fmaxf(m0, __shfl_xor_sync(0xffffffffu, m0, 2));
    m1 = fmaxf(m1, __shfl_xor_sync(0xffffffffu, m1, 1));
    m1 = fmaxf(m1, __shfl_xor_sync(0xffffffffu, m1, 2));
    if ((lane & 3) == 0) {
        red[r0 * 8 + (wid & 3)] = m0;
        red[r1 * 8 + (wid & 3)] = m1;
    }
    __syncthreads();
    float mx0 = fmaxf(fmaxf(red[r0 * 8 + 0], red[r0 * 8 + 1]),
                      fmaxf(red[r0 * 8 + 2], red[r0 * 8 + 3]));
    float mx1 = fmaxf(fmaxf(red[r1 * 8 + 0], red[r1 * 8 + 1]),
                      fmaxf(red[r1 * 8 + 2], red[r1 * 8 + 3]));
    float e[3][4], sum0 = 0.f, sum1 = 0.f;
#pragma unroll
    for (int j = 0; j < 3; j++) {
        e[j][0] = __expf(sv[j][0] - mx0);
        e[j][1] = __expf(sv[j][1] - mx0);
        e[j][2] = __expf(sv[j][2] - mx1);
        e[j][3] = __expf(sv[j][3] - mx1);
        sum0 += e[j][0] + e[j][1];
        sum1 += e[j][2] + e[j][3];
    }
    sum0 += __shfl_xor_sync(0xffffffffu, sum0, 1);
    sum0 += __shfl_xor_sync(0xffffffffu, sum0, 2);
    sum1 += __shfl_xor_sync(0xffffffffu, sum1, 1);
    sum1 += __shfl_xor_sync(0xffffffffu, sum1, 2);
    if ((lane & 3) == 0) {
        red[r0 * 8 + 4 + (wid & 3)] = sum0;
        red[r1 * 8 + 4 + (wid & 3)] = sum1;
    }
    __syncthreads();
    float inv0 = 1.f / (red[r0 * 8 + 4] + red[r0 * 8 + 5] + red[r0 * 8 + 6] + red[r0 * 8 + 7]);
    float inv1 = 1.f / (red[r1 * 8 + 4] + red[r1 * 8 + 5] + red[r1 * 8 + 6] + red[r1 * 8 + 7]);

    // P -> smem hi/lo
#pragma unroll
    for (int j = 0; j < 3; j++) {
        int nb = (nfb + j) * 8 + (lane & 3) * 2;
        uint32_t h0, l0, h1, l1;
        split2h(e[j][0] * inv0, e[j][1] * inv0, h0, l0);
        split2h(e[j][2] * inv1, e[j][3] * inv1, h1, l1);
        *reinterpret_cast<uint32_t*>(sm + A_PH + r0 * VT_ROW + nb * 2) = h0;
        *reinterpret_cast<uint32_t*>(sm + A_PL + r0 * VT_ROW + nb * 2) = l0;
        *reinterpret_cast<uint32_t*>(sm + A_PH + r1 * VT_ROW + nb * 2) = h1;
        *reinterpret_cast<uint32_t*>(sm + A_PL + r1 * VT_ROW + nb * 2) = l1;
    }
    __syncthreads();

    // O = P*V  (V loaded with ldmatrix.trans from natural [t][c] layout)
    const int nc = wid & 3;
    float oacc[4] = {0.f, 0.f, 0.f, 0.f};
#pragma unroll
    for (int kf = 0; kf < 6; kf++) {
        uint32_t ph[4], pl[4], vv[2];
        uint32_t poff = (uint32_t)((mf * 16 + lm_row) * VT_ROW) + kf * 32 + lm_chunk;
        LDM_X4(ph, sb + A_PH + poff);
        LDM_X4(pl, sb + A_PL + poff);
        uint32_t voff = (uint32_t)((kf * 16 + (lane & 15)) * QK_ROW) + nc * 16;
        LDM_X2_T(vv, sb + A_V + voff);
        MMA_F16(oacc, ph, vv);
        MMA_F16(oacc, pl, vv);
    }

    // gate by G, split hi/lo, store
    {
        int gcol = h * 32 + nc * 8 + (lane & 3) * 2;
        size_t e0 = (size_t)(b * S_ + s0 + r0) * 256 + gcol;
        size_t e1 = (size_t)(b * S_ + s0 + r1) * 256 + gcol;
        float2 gA = *reinterpret_cast<const float2*>(g_G + e0);
        float2 gB = *reinterpret_cast<const float2*>(g_G + e1);
        uint32_t h0, l0, h1, l1;
        split2h(oacc[0] * gA.x, oacc[1] * gA.y, h0, l0);
        split2h(oacc[2] * gB.x, oacc[3] * gB.y, h1, l1);
        *reinterpret_cast<uint32_t*>(g_Oh + e0) = h0;
        *reinterpret_cast<uint32_t*>(g_Ol + e0) = l0;
        *reinterpret_cast<uint32_t*>(g_Oh + e1) = h1;
        *reinterpret_cast<uint32_t*>(g_Ol + e1) = l1;
    }
}

// ============================================================
extern "C" void kernel_launch(void* const* d_in, const int* in_sizes, int n_in,
                              void* d_out, int out_size) {
    const float* Qin = (const float*)d_in[0];
    const float* Kin = (const float*)d_in[1];
    const float* Vin = (const float*)d_in[2];
    const float* QT  = (const float*)d_in[3];
    const float* KT  = (const float*)d_in[4];
    const float* VT  = (const float*)d_in[5];
    const float* GW  = (const float*)d_in[6];
    const float* Gb  = (const float*)d_in[7];
    const float* OW  = (const float*)d_in[8];
    const float* Ob  = (const float*)d_in[9];
    float* out = (float*)d_out;

    cudaFuncSetAttribute(proj_kernel, cudaFuncAttributeMaxDynamicSharedMemorySize, SMEM_PROJ);
    cudaFuncSetAttribute(out_kernel,  cudaFuncAttributeMaxDynamicSharedMemorySize, SMEM_OUT);

    prep_all<<<3392, 256>>>(Qin, Kin, Vin, QT, KT, VT, GW, OW);
    proj_kernel<<<dim3(2, 64, 4), 256, SMEM_PROJ>>>(Gb);
    attn_kernel<<<dim3(S_ / 32, H_, B_), 256>>>();
    out_kernel<<<dim3(4, 64, 1), 256, SMEM_OUT>>>(Ob, out);
}

// round 8
// speedup vs baseline: 4.2796x; 1.0348x over previous
#include <cuda_runtime.h>
#include <cuda_fp16.h>
#include <math.h>
#include <stdint.h>

#define B_  2
#define S_  2048
#define D_  256
#define H_  8
#define C_  32
#define OUT_ 256
#define WIN_ 32
#define M_  (B_ * S_)

// -------- device scratch --------
__device__ __align__(16) __half g_X [3 * M_ * D_];   // Qin,Kin,Vin single fp16
__device__ __align__(16) __half g_Wh[5 * 256 * 256]; // weights hi  ([n][k])
__device__ __align__(16) __half g_Wl[5 * 256 * 256]; // weights lo
__device__ __align__(16) __half g_Qh[M_ * D_], g_Ql[M_ * D_];  // Q split (for QK accuracy)
__device__ __align__(16) __half g_K [M_ * D_];
__device__ __align__(16) __half g_V [M_ * D_];
__device__ __align__(16) float  g_G [M_ * D_];
__device__ __align__(16) __half g_O [M_ * D_];       // gated attention output, single fp16

// ================= helpers =================
__device__ __forceinline__ uint32_t smem_u32(const void* p) {
    uint32_t a;
    asm("{ .reg .u64 t; cvta.to.shared.u64 t, %1; cvt.u32.u64 %0, t; }" : "=r"(a) : "l"(p));
    return a;
}
#define LDM_X4(r, addr) \
    asm volatile("ldmatrix.sync.aligned.m8n8.x4.shared.b16 {%0,%1,%2,%3}, [%4];" \
        : "=r"((r)[0]), "=r"((r)[1]), "=r"((r)[2]), "=r"((r)[3]) : "r"(addr))
#define LDM_X2(r, addr) \
    asm volatile("ldmatrix.sync.aligned.m8n8.x2.shared.b16 {%0,%1}, [%2];" \
        : "=r"((r)[0]), "=r"((r)[1]) : "r"(addr))
#define LDM_X2_T(r, addr) \
    asm volatile("ldmatrix.sync.aligned.m8n8.x2.trans.shared.b16 {%0,%1}, [%2];" \
        : "=r"((r)[0]), "=r"((r)[1]) : "r"(addr))
#define MMA_F16(c, a, b) \
    asm volatile("mma.sync.aligned.m16n8k16.row.col.f32.f16.f16.f32 " \
        "{%0,%1,%2,%3}, {%4,%5,%6,%7}, {%8,%9}, {%0,%1,%2,%3};" \
        : "+f"((c)[0]), "+f"((c)[1]), "+f"((c)[2]), "+f"((c)[3]) \
        : "r"((a)[0]), "r"((a)[1]), "r"((a)[2]), "r"((a)[3]), "r"((b)[0]), "r"((b)[1]))
#define CP_ASYNC16(dst, src) \
    asm volatile("cp.async.cg.shared.global [%0], [%1], 16;" :: "r"(dst), "l"(src))
#define CP_COMMIT() asm volatile("cp.async.commit_group;" ::: "memory")
#define CP_WAIT(n)  asm volatile("cp.async.wait_group %0;" :: "n"(n) : "memory")

__device__ __forceinline__ void split2h(float a, float b, uint32_t& h, uint32_t& l) {
    __half2 hi2 = __floats2half2_rn(a, b);
    float ra = a - __low2float(hi2);
    float rb = b - __high2float(hi2);
    __half2 lo2 = __floats2half2_rn(ra, rb);
    h = *reinterpret_cast<uint32_t*>(&hi2);
    l = *reinterpret_cast<uint32_t*>(&lo2);
}

// ================= fused prep kernel =================
// [0,3072): inputs fp32->fp16 single; [3072,3200): GW/OW split; [3200,3392): QT/KT/VT transpose+split
__global__ void prep_all(const float* __restrict__ Qin, const float* __restrict__ Kin,
                         const float* __restrict__ Vin, const float* __restrict__ QT,
                         const float* __restrict__ KT,  const float* __restrict__ VT,
                         const float* __restrict__ GW,  const float* __restrict__ OW) {
    int blk = blockIdx.x;
    if (blk < 3072) {
        int z = blk >> 10;
        int bx = blk & 1023;
        const float* src = (z == 0) ? Qin : (z == 1) ? Kin : Vin;
        size_t base = (size_t)z * (M_ * D_);
        int i = bx * 256 + threadIdx.x;
        float4 v = reinterpret_cast<const float4*>(src)[i];
        __half2 a = __floats2half2_rn(v.x, v.y);
        __half2 b = __floats2half2_rn(v.z, v.w);
        reinterpret_cast<uint2*>(g_X + base)[i] =
            make_uint2(*reinterpret_cast<uint32_t*>(&a), *reinterpret_cast<uint32_t*>(&b));
    } else if (blk < 3200) {
        int t = blk - 3072;
        int z = t >> 6;
        int bx = t & 63;
        const float* src = (z == 0) ? GW : OW;
        size_t base = (size_t)(3 + z) * 65536;
        int i = bx * 256 + threadIdx.x;
        float4 v = reinterpret_cast<const float4*>(src)[i];
        uint32_t h0, l0, h1, l1;
        split2h(v.x, v.y, h0, l0);
        split2h(v.z, v.w, h1, l1);
        reinterpret_cast<uint2*>(g_Wh + base)[i] = make_uint2(h0, h1);
        reinterpret_cast<uint2*>(g_Wl + base)[i] = make_uint2(l0, l1);
    } else {
        int t = blk - 3200;
        int z = t >> 6;
        int ky = (t >> 3) & 7;
        int nx = t & 7;
        const float* src = (z == 0) ? QT : (z == 1) ? KT : VT;
        size_t base = (size_t)z * 65536;
        __shared__ float tr[32][33];
        int tx = threadIdx.x & 31, ty = threadIdx.x >> 5;
        int k0 = ky * 32, n0 = nx * 32;
#pragma unroll
        for (int r = 0; r < 4; r++)
            tr[ty + r * 8][tx] = src[(size_t)(k0 + ty + r * 8) * 256 + n0 + tx];
        __syncthreads();
#pragma unroll
        for (int r = 0; r < 4; r++) {
            int n = n0 + ty + r * 8, k = k0 + tx;
            float v = tr[tx][ty + r * 8];
            __half h = __float2half(v);
            g_Wh[base + (size_t)n * 256 + k] = h;
            g_Wl[base + (size_t)n * 256 + k] = __float2half(v - __half2float(h));
        }
    }
}

// ================= fp16 MMA GEMM: A single, B split hi/lo, 4-stage =================
#define G_ROW  80
#define GBM    64
#define GBN    64
#define STAGE_ ((GBM + 2 * GBN) * G_ROW)   // 15360
#define SMEM_GEMM (4 * STAGE_)             // 61440

// MODE: 0 = split half out, 1 = f32+bias+sigmoid, 2 = f32+bias, 3 = single half out
template <int MODE>
__device__ __forceinline__ void gemm_core(const __half* __restrict__ A,
                                          const __half* __restrict__ Bh, const __half* __restrict__ Bl,
                                          const float* __restrict__ bias,
                                          float* __restrict__ Yf,
                                          __half* __restrict__ Yh, __half* __restrict__ Yl) {
    extern __shared__ char smem[];
    const uint32_t sb = smem_u32(smem);
    const int tid = threadIdx.x, wid = tid >> 5, lane = tid & 31;

    // 8 warps: 2 along M, 4 along N -> warp tile 32 x 16 (NF=2)
    const int warp_m = wid & 1, warp_n = wid >> 1;
    const int m0 = blockIdx.y * GBM, n0 = blockIdx.x * GBN;
    const int lm_row = lane & 15, lm_chunk = (lane >> 4) * 16;

    float acc[2][2][4];
#pragma unroll
    for (int i = 0; i < 2; i++)
#pragma unroll
        for (int j = 0; j < 2; j++)
#pragma unroll
            for (int q = 0; q < 4; q++) acc[i][j][q] = 0.f;

    auto stage = [&](int kc, int buf) {
#pragma unroll
        for (int task = tid; task < (GBM + 2 * GBN) * 4; task += 256) {
            const __half* s;
            uint32_t dbase;
            int row, ch = task & 3;
            if (task < GBM * 4) {
                row = task >> 2;
                s = A + (size_t)(m0 + row) * 256 + kc * 32 + ch * 8;
                dbase = 0;
            } else if (task < (GBM + GBN) * 4) {
                row = (task - GBM * 4) >> 2;
                s = Bh + (size_t)(n0 + row) * 256 + kc * 32 + ch * 8;
                dbase = GBM * G_ROW;
            } else {
                row = (task - (GBM + GBN) * 4) >> 2;
                s = Bl + (size_t)(n0 + row) * 256 + kc * 32 + ch * 8;
                dbase = (GBM + GBN) * G_ROW;
            }
            CP_ASYNC16(sb + buf * STAGE_ + dbase + row * G_ROW + ch * 16, s);
        }
    };

    stage(0, 0); CP_COMMIT();
    stage(1, 1); CP_COMMIT();
    stage(2, 2); CP_COMMIT();

    for (int kc = 0; kc < 8; kc++) {
        if (kc < 6) CP_WAIT(2);
        else if (kc == 6) CP_WAIT(1);
        else CP_WAIT(0);
        __syncthreads();

        const uint32_t bb = sb + (kc & 3) * STAGE_;
#pragma unroll
        for (int ks = 0; ks < 2; ks++) {
            const uint32_t kbyte = ks * 32 + lm_chunk;
            uint32_t a[2][4], bh[2][2], bl[2][2];
#pragma unroll
            for (int mf = 0; mf < 2; mf++) {
                uint32_t off = (uint32_t)((warp_m * 32 + mf * 16 + lm_row) * G_ROW) + kbyte;
                LDM_X4(a[mf], bb + off);
            }
            {
                uint32_t off = (uint32_t)((warp_n * 16 + lm_row) * G_ROW) + kbyte;
                uint32_t th[4], tl[4];
                LDM_X4(th, bb + GBM * G_ROW + off);
                LDM_X4(tl, bb + (GBM + GBN) * G_ROW + off);
                bh[0][0] = th[0]; bh[0][1] = th[2];
                bh[1][0] = th[1]; bh[1][1] = th[3];
                bl[0][0] = tl[0]; bl[0][1] = tl[2];
                bl[1][0] = tl[1]; bl[1][1] = tl[3];
            }
#pragma unroll
            for (int mf = 0; mf < 2; mf++)
#pragma unroll
                for (int nf = 0; nf < 2; nf++) {
                    MMA_F16(acc[mf][nf], a[mf], bh[nf]);
                    MMA_F16(acc[mf][nf], a[mf], bl[nf]);
                }
        }

        if (kc + 3 < 8) { stage(kc + 3, (kc + 3) & 3); CP_COMMIT(); }
    }

    // epilogue
#pragma unroll
    for (int mf = 0; mf < 2; mf++) {
        int row = m0 + warp_m * 32 + mf * 16 + (lane >> 2);
#pragma unroll
        for (int nf = 0; nf < 2; nf++) {
            int col = n0 + warp_n * 16 + nf * 8 + (lane & 3) * 2;
            float v0 = acc[mf][nf][0], v1 = acc[mf][nf][1];
            float v2 = acc[mf][nf][2], v3 = acc[mf][nf][3];
            if (MODE == 1 || MODE == 2) {
                float b0 = bias[col], b1 = bias[col + 1];
                v0 += b0; v1 += b1; v2 += b0; v3 += b1;
                if (MODE == 1) {
                    v0 = 1.f / (1.f + __expf(-v0));
                    v1 = 1.f / (1.f + __expf(-v1));
                    v2 = 1.f / (1.f + __expf(-v2));
                    v3 = 1.f / (1.f + __expf(-v3));
                }
                *reinterpret_cast<float2*>(Yf + (size_t)row * 256 + col)       = make_float2(v0, v1);
                *reinterpret_cast<float2*>(Yf + (size_t)(row + 8) * 256 + col) = make_float2(v2, v3);
            } else if (MODE == 0) {
                uint32_t h0, l0, h1, l1;
                split2h(v0, v1, h0, l0);
                split2h(v2, v3, h1, l1);
                *reinterpret_cast<uint32_t*>(Yh + (size_t)row * 256 + col)       = h0;
                *reinterpret_cast<uint32_t*>(Yl + (size_t)row * 256 + col)       = l0;
                *reinterpret_cast<uint32_t*>(Yh + (size_t)(row + 8) * 256 + col) = h1;
                *reinterpret_cast<uint32_t*>(Yl + (size_t)(row + 8) * 256 + col) = l1;
            } else {
                __half2 a2 = __floats2half2_rn(v0, v1);
                __half2 b2 = __floats2half2_rn(v2, v3);
                *reinterpret_cast<uint32_t*>(Yh + (size_t)row * 256 + col)       = *reinterpret_cast<uint32_t*>(&a2);
                *reinterpret_cast<uint32_t*>(Yh + (size_t)(row + 8) * 256 + col) = *reinterpret_cast<uint32_t*>(&b2);
            }
        }
    }
}

__global__ void __launch_bounds__(256, 3)
proj_kernel(const float* __restrict__ Gb) {
    int z = blockIdx.z;
    int xslot = (z == 3) ? 2 : z;
    const __half* A  = g_X + (size_t)xslot * (M_ * D_);
    const __half* Bh = g_Wh + (size_t)z * 65536;
    const __half* Bl = g_Wl + (size_t)z * 65536;
    if (z == 0)      gemm_core<0>(A, Bh, Bl, nullptr, nullptr, g_Qh, g_Ql);
    else if (z == 1) gemm_core<3>(A, Bh, Bl, nullptr, nullptr, g_K, nullptr);
    else if (z == 2) gemm_core<3>(A, Bh, Bl, nullptr, nullptr, g_V, nullptr);
    else             gemm_core<1>(A, Bh, Bl, Gb, g_G, nullptr, nullptr);
}

__global__ void __launch_bounds__(256, 3)
out_kernel(const float* __restrict__ Ob, float* __restrict__ out) {
    gemm_core<2>(g_O, g_Wh + 4 * 65536, g_Wl + 4 * 65536, Ob, out, nullptr, nullptr);
}

// ================= fp16 tensor-core local-window attention =================
#define A_QH 0
#define A_QL 2560
#define A_K  5120
#define A_V  12800
#define A_PH 20480
#define A_PL 27136
#define A_RED 33792
#define A_TOTAL 34816
#define QK_ROW 80
#define VT_ROW 208

__global__ void __launch_bounds__(256)
attn_kernel() {
    __shared__ __align__(16) char sm[A_TOTAL];
    const uint32_t sb = smem_u32(sm);
    float* red = reinterpret_cast<float*>(sm + A_RED);

    const int b = blockIdx.z, h = blockIdx.y, s0 = blockIdx.x * 32;
    const int tid = threadIdx.x, wid = tid >> 5, lane = tid & 31;
    const int lm_row = lane & 15, lm_chunk = (lane >> 4) * 16;

    for (int i = tid; i < 384; i += 256) {
        int row = i >> 2, ch = i & 3;
        int t = s0 - 32 + row;
        uint4 vk = make_uint4(0, 0, 0, 0), vv = vk;
        if (t >= 0 && t < S_) {
            size_t e = (size_t)(b * S_ + t) * 256 + h * 32 + ch * 8;
            vk = *reinterpret_cast<const uint4*>(g_K + e);
            vv = *reinterpret_cast<const uint4*>(g_V + e);
        }
        *reinterpret_cast<uint4*>(sm + A_K + row * QK_ROW + ch * 16) = vk;
        *reinterpret_cast<uint4*>(sm + A_V + row * QK_ROW + ch * 16) = vv;
    }
    for (int i = tid; i < 128; i += 256) {
        int row = i >> 2, ch = i & 3;
        size_t e = (size_t)(b * S_ + s0 + row) * 256 + h * 32 + ch * 8;
        *reinterpret_cast<uint4*>(sm + A_QH + row * QK_ROW + ch * 16) =
            *reinterpret_cast<const uint4*>(g_Qh + e);
        *reinterpret_cast<uint4*>(sm + A_QL + row * QK_ROW + ch * 16) =
            *reinterpret_cast<const uint4*>(g_Ql + e);
    }
    __syncthreads();

    const int mf = wid >> 2;
    const int nfb = (wid & 3) * 3;
    float sc[3][4];
#pragma unroll
    for (int j = 0; j < 3; j++)
#pragma unroll
        for (int q = 0; q < 4; q++) sc[j][q] = 0.f;

#pragma unroll
    for (int kf = 0; kf < 2; kf++) {
        uint32_t qh[4], ql[4];
        uint32_t aoff = (uint32_t)((mf * 16 + lm_row) * QK_ROW) + kf * 32 + lm_chunk;
        LDM_X4(qh, sb + A_QH + aoff);
        LDM_X4(ql, sb + A_QL + aoff);
#pragma unroll
        for (int j = 0; j < 3; j++) {
            uint32_t kk[2];
            uint32_t boff = (uint32_t)(((nfb + j) * 8 + (lane & 7)) * QK_ROW) + kf * 32 +
                            (((lane >> 3) & 1) * 16);
            LDM_X2(kk, sb + A_K + boff);
            MMA_F16(sc[j], qh, kk);
            MMA_F16(sc[j], ql, kk);
        }
    }

    const float rsC = 0.17677669529663689f;
    const int r0 = mf * 16 + (lane >> 2);
    const int r1 = r0 + 8;
    float sv[3][4];
#pragma unroll
    for (int j = 0; j < 3; j++) {
        int nb = (nfb + j) * 8 + (lane & 3) * 2;
#pragma unroll
        for (int q = 0; q < 4; q++) {
            int n = nb + (q & 1);
            int row = (q < 2) ? r0 : r1;
            int t = s0 - 32 + n;
            bool ok = (n >= row) && (n <= row + 64) && (t >= 0) && (t < S_);
            sv[j][q] = ok ? sc[j][q] * rsC : -1e30f;
        }
    }
    float m0 = -1e30f, m1 = -1e30f;
#pragma unroll
    for (int j = 0; j < 3; j++) {
        m0 = fmaxf(m0, fmaxf(sv[j][0], sv[j][1]));
        m1 = fmaxf(m1, fmaxf(sv[j][2], sv[j][3]));
    }
    m0 = fmaxf(m0, __shfl_xor_sync(0xffffffffu, m0, 1));
    m0 = fmaxf(m0, __shfl_xor_sync(0xffffffffu, m0, 2));
    m1 = fmaxf(m1, __shfl_xor_sync(0xffffffffu, m1, 1));
    m1 = fmaxf(m1, __shfl_xor_sync(0xffffffffu, m1, 2));
    if ((lane & 3) == 0) {
        red[r0 * 8 + (wid & 3)] = m0;
        red[r1 * 8 + (wid & 3)] = m1;
    }
    __syncthreads();
    float mx0 = fmaxf(fmaxf(red[r0 * 8 + 0], red[r0 * 8 + 1]),
                      fmaxf(red[r0 * 8 + 2], red[r0 * 8 + 3]));
    float mx1 = fmaxf(fmaxf(red[r1 * 8 + 0], red[r1 * 8 + 1]),
                      fmaxf(red[r1 * 8 + 2], red[r1 * 8 + 3]));
    float e[3][4], sum0 = 0.f, sum1 = 0.f;
#pragma unroll
    for (int j = 0; j < 3; j++) {
        e[j][0] = __expf(sv[j][0] - mx0);
        e[j][1] = __expf(sv[j][1] - mx0);
        e[j][2] = __expf(sv[j][2] - mx1);
        e[j][3] = __expf(sv[j][3] - mx1);
        sum0 += e[j][0] + e[j][1];
        sum1 += e[j][2] + e[j][3];
    }
    sum0 += __shfl_xor_sync(0xffffffffu, sum0, 1);
    sum0 += __shfl_xor_sync(0xffffffffu, sum0, 2);
    sum1 += __shfl_xor_sync(0xffffffffu, sum1, 1);
    sum1 += __shfl_xor_sync(0xffffffffu, sum1, 2);
    if ((lane & 3) == 0) {
        red[r0 * 8 + 4 + (wid & 3)] = sum0;
        red[r1 * 8 + 4 + (wid & 3)] = sum1;
    }
    __syncthreads();
    float inv0 = 1.f / (red[r0 * 8 + 4] + red[r0 * 8 + 5] + red[r0 * 8 + 6] + red[r0 * 8 + 7]);
    float inv1 = 1.f / (red[r1 * 8 + 4] + red[r1 * 8 + 5] + red[r1 * 8 + 6] + red[r1 * 8 + 7]);

#pragma unroll
    for (int j = 0; j < 3; j++) {
        int nb = (nfb + j) * 8 + (lane & 3) * 2;
        uint32_t h0, l0, h1, l1;
        split2h(e[j][0] * inv0, e[j][1] * inv0, h0, l0);
        split2h(e[j][2] * inv1, e[j][3] * inv1, h1, l1);
        *reinterpret_cast<uint32_t*>(sm + A_PH + r0 * VT_ROW + nb * 2) = h0;
        *reinterpret_cast<uint32_t*>(sm + A_PL + r0 * VT_ROW + nb * 2) = l0;
        *reinterpret_cast<uint32_t*>(sm + A_PH + r1 * VT_ROW + nb * 2) = h1;
        *reinterpret_cast<uint32_t*>(sm + A_PL + r1 * VT_ROW + nb * 2) = l1;
    }
    __syncthreads();

    const int nc = wid & 3;
    float oacc[4] = {0.f, 0.f, 0.f, 0.f};
#pragma unroll
    for (int kf = 0; kf < 6; kf++) {
        uint32_t ph[4], pl[4], vv[2];
        uint32_t poff = (uint32_t)((mf * 16 + lm_row) * VT_ROW) + kf * 32 + lm_chunk;
        LDM_X4(ph, sb + A_PH + poff);
        LDM_X4(pl, sb + A_PL + poff);
        uint32_t voff = (uint32_t)((kf * 16 + (lane & 15)) * QK_ROW) + nc * 16;
        LDM_X2_T(vv, sb + A_V + voff);
        MMA_F16(oacc, ph, vv);
        MMA_F16(oacc, pl, vv);
    }

    // gate by G, store single fp16
    {
        int gcol = h * 32 + nc * 8 + (lane & 3) * 2;
        size_t e0 = (size_t)(b * S_ + s0 + r0) * 256 + gcol;
        size_t e1 = (size_t)(b * S_ + s0 + r1) * 256 + gcol;
        float2 gA = *reinterpret_cast<const float2*>(g_G + e0);
        float2 gB = *reinterpret_cast<const float2*>(g_G + e1);
        __half2 o0 = __floats2half2_rn(oacc[0] * gA.x, oacc[1] * gA.y);
        __half2 o1 = __floats2half2_rn(oacc[2] * gB.x, oacc[3] * gB.y);
        *reinterpret_cast<uint32_t*>(g_O + e0) = *reinterpret_cast<uint32_t*>(&o0);
        *reinterpret_cast<uint32_t*>(g_O + e1) = *reinterpret_cast<uint32_t*>(&o1);
    }
}

// ============================================================
extern "C" void kernel_launch(void* const* d_in, const int* in_sizes, int n_in,
                              void* d_out, int out_size) {
    const float* Qin = (const float*)d_in[0];
    const float* Kin = (const float*)d_in[1];
    const float* Vin = (const float*)d_in[2];
    const float* QT  = (const float*)d_in[3];
    const float* KT  = (const float*)d_in[4];
    const float* VT  = (const float*)d_in[5];
    const float* GW  = (const float*)d_in[6];
    const float* Gb  = (const float*)d_in[7];
    const float* OW  = (const float*)d_in[8];
    const float* Ob  = (const float*)d_in[9];
    float* out = (float*)d_out;

    cudaFuncSetAttribute(proj_kernel, cudaFuncAttributeMaxDynamicSharedMemorySize, SMEM_GEMM);
    cudaFuncSetAttribute(out_kernel,  cudaFuncAttributeMaxDynamicSharedMemorySize, SMEM_GEMM);

    prep_all<<<3392, 256>>>(Qin, Kin, Vin, QT, KT, VT, GW, OW);
    proj_kernel<<<dim3(4, 64, 4), 256, SMEM_GEMM>>>(Gb);
    attn_kernel<<<dim3(S_ / 32, H_, B_), 256>>>();
    out_kernel<<<dim3(4, 64, 1), 256, SMEM_GEMM>>>(Ob, out);
}

// round 9
// speedup vs baseline: 4.4338x; 1.0360x over previous
#include <cuda_runtime.h>
#include <cuda_fp16.h>
#include <math.h>
#include <stdint.h>

#define B_  2
#define S_  2048
#define D_  256
#define H_  8
#define C_  32
#define OUT_ 256
#define WIN_ 32
#define M_  (B_ * S_)

// -------- device scratch --------
__device__ __align__(16) __half g_X [3 * M_ * D_];   // Qin,Kin,Vin single fp16
__device__ __align__(16) __half g_Wh[5 * 256 * 256]; // weights hi  ([n][k])
__device__ __align__(16) __half g_Wl[5 * 256 * 256]; // weights lo
__device__ __align__(16) __half g_Qh[M_ * D_], g_Ql[M_ * D_];
__device__ __align__(16) __half g_K [M_ * D_];
__device__ __align__(16) __half g_V [M_ * D_];
__device__ __align__(16) float  g_G [M_ * D_];
__device__ __align__(16) __half g_O [M_ * D_];

// ================= helpers =================
__device__ __forceinline__ uint32_t smem_u32(const void* p) {
    uint32_t a;
    asm("{ .reg .u64 t; cvta.to.shared.u64 t, %1; cvt.u32.u64 %0, t; }" : "=r"(a) : "l"(p));
    return a;
}
#define LDM_X4(r, addr) \
    asm volatile("ldmatrix.sync.aligned.m8n8.x4.shared.b16 {%0,%1,%2,%3}, [%4];" \
        : "=r"((r)[0]), "=r"((r)[1]), "=r"((r)[2]), "=r"((r)[3]) : "r"(addr))
#define LDM_X2(r, addr) \
    asm volatile("ldmatrix.sync.aligned.m8n8.x2.shared.b16 {%0,%1}, [%2];" \
        : "=r"((r)[0]), "=r"((r)[1]) : "r"(addr))
#define LDM_X2_T(r, addr) \
    asm volatile("ldmatrix.sync.aligned.m8n8.x2.trans.shared.b16 {%0,%1}, [%2];" \
        : "=r"((r)[0]), "=r"((r)[1]) : "r"(addr))
#define MMA_F16(c, a, b) \
    asm volatile("mma.sync.aligned.m16n8k16.row.col.f32.f16.f16.f32 " \
        "{%0,%1,%2,%3}, {%4,%5,%6,%7}, {%8,%9}, {%0,%1,%2,%3};" \
        : "+f"((c)[0]), "+f"((c)[1]), "+f"((c)[2]), "+f"((c)[3]) \
        : "r"((a)[0]), "r"((a)[1]), "r"((a)[2]), "r"((a)[3]), "r"((b)[0]), "r"((b)[1]))
#define CP_ASYNC16(dst, src) \
    asm volatile("cp.async.cg.shared.global [%0], [%1], 16;" :: "r"(dst), "l"(src))
#define CP_COMMIT() asm volatile("cp.async.commit_group;" ::: "memory")
#define CP_WAIT(n)  asm volatile("cp.async.wait_group %0;" :: "n"(n) : "memory")

__device__ __forceinline__ void split2h(float a, float b, uint32_t& h, uint32_t& l) {
    __half2 hi2 = __floats2half2_rn(a, b);
    float ra = a - __low2float(hi2);
    float rb = b - __high2float(hi2);
    __half2 lo2 = __floats2half2_rn(ra, rb);
    h = *reinterpret_cast<uint32_t*>(&hi2);
    l = *reinterpret_cast<uint32_t*>(&lo2);
}

// ================= fused prep kernel =================
__global__ void prep_all(const float* __restrict__ Qin, const float* __restrict__ Kin,
                         const float* __restrict__ Vin, const float* __restrict__ QT,
                         const float* __restrict__ KT,  const float* __restrict__ VT,
                         const float* __restrict__ GW,  const float* __restrict__ OW) {
    int blk = blockIdx.x;
    if (blk < 3072) {
        int z = blk >> 10;
        int bx = blk & 1023;
        const float* src = (z == 0) ? Qin : (z == 1) ? Kin : Vin;
        size_t base = (size_t)z * (M_ * D_);
        int i = bx * 256 + threadIdx.x;
        float4 v = reinterpret_cast<const float4*>(src)[i];
        __half2 a = __floats2half2_rn(v.x, v.y);
        __half2 b = __floats2half2_rn(v.z, v.w);
        reinterpret_cast<uint2*>(g_X + base)[i] =
            make_uint2(*reinterpret_cast<uint32_t*>(&a), *reinterpret_cast<uint32_t*>(&b));
    } else if (blk < 3200) {
        int t = blk - 3072;
        int z = t >> 6;
        int bx = t & 63;
        const float* src = (z == 0) ? GW : OW;
        size_t base = (size_t)(3 + z) * 65536;
        int i = bx * 256 + threadIdx.x;
        float4 v = reinterpret_cast<const float4*>(src)[i];
        uint32_t h0, l0, h1, l1;
        split2h(v.x, v.y, h0, l0);
        split2h(v.z, v.w, h1, l1);
        reinterpret_cast<uint2*>(g_Wh + base)[i] = make_uint2(h0, h1);
        reinterpret_cast<uint2*>(g_Wl + base)[i] = make_uint2(l0, l1);
    } else {
        int t = blk - 3200;
        int z = t >> 6;
        int ky = (t >> 3) & 7;
        int nx = t & 7;
        const float* src = (z == 0) ? QT : (z == 1) ? KT : VT;
        size_t base = (size_t)z * 65536;
        __shared__ float tr[32][33];
        int tx = threadIdx.x & 31, ty = threadIdx.x >> 5;
        int k0 = ky * 32, n0 = nx * 32;
#pragma unroll
        for (int r = 0; r < 4; r++)
            tr[ty + r * 8][tx] = src[(size_t)(k0 + ty + r * 8) * 256 + n0 + tx];
        __syncthreads();
#pragma unroll
        for (int r = 0; r < 4; r++) {
            int n = n0 + ty + r * 8, k = k0 + tx;
            float v = tr[tx][ty + r * 8];
            __half h = __float2half(v);
            g_Wh[base + (size_t)n * 256 + k] = h;
            g_Wl[base + (size_t)n * 256 + k] = __float2half(v - __half2float(h));
        }
    }
}

// ================= fp16 MMA GEMM: BK=128, both chunks fully prefetched =================
#define G_ROW  272                          // 128 halves = 256B + 16 pad
#define GBM    64
#define GBN    64
#define STAGE_ ((GBM + 2 * GBN) * G_ROW)    // 192*272 = 52224
#define SMEM_GEMM (2 * STAGE_)              // 104448

// MODE: 0 = split half out, 1 = f32+bias+sigmoid, 2 = f32+bias, 3 = single half out
template <int MODE>
__device__ __forceinline__ void gemm_core(const __half* __restrict__ A,
                                          const __half* __restrict__ Bh, const __half* __restrict__ Bl,
                                          const float* __restrict__ bias,
                                          float* __restrict__ Yf,
                                          __half* __restrict__ Yh, __half* __restrict__ Yl) {
    extern __shared__ char smem[];
    const uint32_t sb = smem_u32(smem);
    const int tid = threadIdx.x, wid = tid >> 5, lane = tid & 31;

    // 8 warps: 2 along M, 4 along N -> warp tile 32 x 16
    const int warp_m = wid & 1, warp_n = wid >> 1;
    const int m0 = blockIdx.y * GBM, n0 = blockIdx.x * GBN;
    const int lm_row = lane & 15, lm_chunk = (lane >> 4) * 16;

    float acc[2][2][4];
#pragma unroll
    for (int i = 0; i < 2; i++)
#pragma unroll
        for (int j = 0; j < 2; j++)
#pragma unroll
            for (int q = 0; q < 4; q++) acc[i][j][q] = 0.f;

    // stage one BK=128 chunk (192 rows x 256 bytes)
    auto stage = [&](int kc, int buf) {
#pragma unroll
        for (int task = tid; task < 3072; task += 256) {
            int row = task >> 4;          // 0..191
            int ch  = task & 15;          // 16B chunk within 256B row
            const __half* s;
            uint32_t dbase;
            if (row < GBM) {
                s = A + (size_t)(m0 + row) * 256 + kc * 128 + ch * 8;
                dbase = (uint32_t)(row * G_ROW);
            } else if (row < GBM + GBN) {
                int r = row - GBM;
                s = Bh + (size_t)(n0 + r) * 256 + kc * 128 + ch * 8;
                dbase = (uint32_t)((GBM + r) * G_ROW);
            } else {
                int r = row - GBM - GBN;
                s = Bl + (size_t)(n0 + r) * 256 + kc * 128 + ch * 8;
                dbase = (uint32_t)((GBM + GBN + r) * G_ROW);
            }
            CP_ASYNC16(sb + buf * STAGE_ + dbase + ch * 16, s);
        }
    };

    stage(0, 0); CP_COMMIT();
    stage(1, 1); CP_COMMIT();

#pragma unroll
    for (int kc = 0; kc < 2; kc++) {
        if (kc == 0) CP_WAIT(1); else CP_WAIT(0);
        __syncthreads();

        const uint32_t bb = sb + kc * STAGE_;
#pragma unroll
        for (int ks = 0; ks < 8; ks++) {
            const uint32_t kbyte = ks * 32 + lm_chunk;
            uint32_t a[2][4], bh[2][2], bl[2][2];
#pragma unroll
            for (int mf = 0; mf < 2; mf++) {
                uint32_t off = (uint32_t)((warp_m * 32 + mf * 16 + lm_row) * G_ROW) + kbyte;
                LDM_X4(a[mf], bb + off);
            }
            {
                uint32_t off = (uint32_t)((warp_n * 16 + lm_row) * G_ROW) + kbyte;
                uint32_t th[4], tl[4];
                LDM_X4(th, bb + GBM * G_ROW + off);
                LDM_X4(tl, bb + (GBM + GBN) * G_ROW + off);
                bh[0][0] = th[0]; bh[0][1] = th[2];
                bh[1][0] = th[1]; bh[1][1] = th[3];
                bl[0][0] = tl[0]; bl[0][1] = tl[2];
                bl[1][0] = tl[1]; bl[1][1] = tl[3];
            }
#pragma unroll
            for (int mf = 0; mf < 2; mf++)
#pragma unroll
                for (int nf = 0; nf < 2; nf++) {
                    MMA_F16(acc[mf][nf], a[mf], bh[nf]);
                    MMA_F16(acc[mf][nf], a[mf], bl[nf]);
                }
        }
    }

    // epilogue
#pragma unroll
    for (int mf = 0; mf < 2; mf++) {
        int row = m0 + warp_m * 32 + mf * 16 + (lane >> 2);
#pragma unroll
        for (int nf = 0; nf < 2; nf++) {
            int col = n0 + warp_n * 16 + nf * 8 + (lane & 3) * 2;
            float v0 = acc[mf][nf][0], v1 = acc[mf][nf][1];
            float v2 = acc[mf][nf][2], v3 = acc[mf][nf][3];
            if (MODE == 1 || MODE == 2) {
                float b0 = bias[col], b1 = bias[col + 1];
                v0 += b0; v1 += b1; v2 += b0; v3 += b1;
                if (MODE == 1) {
                    v0 = 1.f / (1.f + __expf(-v0));
                    v1 = 1.f / (1.f + __expf(-v1));
                    v2 = 1.f / (1.f + __expf(-v2));
                    v3 = 1.f / (1.f + __expf(-v3));
                }
                *reinterpret_cast<float2*>(Yf + (size_t)row * 256 + col)       = make_float2(v0, v1);
                *reinterpret_cast<float2*>(Yf + (size_t)(row + 8) * 256 + col) = make_float2(v2, v3);
            } else if (MODE == 0) {
                uint32_t h0, l0, h1, l1;
                split2h(v0, v1, h0, l0);
                split2h(v2, v3, h1, l1);
                *reinterpret_cast<uint32_t*>(Yh + (size_t)row * 256 + col)       = h0;
                *reinterpret_cast<uint32_t*>(Yl + (size_t)row * 256 + col)       = l0;
                *reinterpret_cast<uint32_t*>(Yh + (size_t)(row + 8) * 256 + col) = h1;
                *reinterpret_cast<uint32_t*>(Yl + (size_t)(row + 8) * 256 + col) = l1;
            } else {
                __half2 a2 = __floats2half2_rn(v0, v1);
                __half2 b2 = __floats2half2_rn(v2, v3);
                *reinterpret_cast<uint32_t*>(Yh + (size_t)row * 256 + col)       = *reinterpret_cast<uint32_t*>(&a2);
                *reinterpret_cast<uint32_t*>(Yh + (size_t)(row + 8) * 256 + col) = *reinterpret_cast<uint32_t*>(&b2);
            }
        }
    }
}

__global__ void __launch_bounds__(256, 2)
proj_kernel(const float* __restrict__ Gb) {
    int z = blockIdx.z;
    int xslot = (z == 3) ? 2 : z;
    const __half* A  = g_X + (size_t)xslot * (M_ * D_);
    const __half* Bh = g_Wh + (size_t)z * 65536;
    const __half* Bl = g_Wl + (size_t)z * 65536;
    if (z == 0)      gemm_core<0>(A, Bh, Bl, nullptr, nullptr, g_Qh, g_Ql);
    else if (z == 1) gemm_core<3>(A, Bh, Bl, nullptr, nullptr, g_K, nullptr);
    else if (z == 2) gemm_core<3>(A, Bh, Bl, nullptr, nullptr, g_V, nullptr);
    else             gemm_core<1>(A, Bh, Bl, Gb, g_G, nullptr, nullptr);
}

__global__ void __launch_bounds__(256, 2)
out_kernel(const float* __restrict__ Ob, float* __restrict__ out) {
    gemm_core<2>(g_O, g_Wh + 4 * 65536, g_Wl + 4 * 65536, Ob, out, nullptr, nullptr);
}

// ================= fp16 tensor-core local-window attention =================
#define A_QH 0
#define A_QL 2560
#define A_K  5120
#define A_V  12800
#define A_PH 20480
#define A_PL 27136
#define A_RED 33792
#define A_TOTAL 34816
#define QK_ROW 80
#define VT_ROW 208

__global__ void __launch_bounds__(256)
attn_kernel() {
    __shared__ __align__(16) char sm[A_TOTAL];
    const uint32_t sb = smem_u32(sm);
    float* red = reinterpret_cast<float*>(sm + A_RED);

    const int b = blockIdx.z, h = blockIdx.y, s0 = blockIdx.x * 32;
    const int tid = threadIdx.x, wid = tid >> 5, lane = tid & 31;
    const int lm_row = lane & 15, lm_chunk = (lane >> 4) * 16;

    for (int i = tid; i < 384; i += 256) {
        int row = i >> 2, ch = i & 3;
        int t = s0 - 32 + row;
        uint4 vk = make_uint4(0, 0, 0, 0), vv = vk;
        if (t >= 0 && t < S_) {
            size_t e = (size_t)(b * S_ + t) * 256 + h * 32 + ch * 8;
            vk = *reinterpret_cast<const uint4*>(g_K + e);
            vv = *reinterpret_cast<const uint4*>(g_V + e);
        }
        *reinterpret_cast<uint4*>(sm + A_K + row * QK_ROW + ch * 16) = vk;
        *reinterpret_cast<uint4*>(sm + A_V + row * QK_ROW + ch * 16) = vv;
    }
    for (int i = tid; i < 128; i += 256) {
        int row = i >> 2, ch = i & 3;
        size_t e = (size_t)(b * S_ + s0 + row) * 256 + h * 32 + ch * 8;
        *reinterpret_cast<uint4*>(sm + A_QH + row * QK_ROW + ch * 16) =
            *reinterpret_cast<const uint4*>(g_Qh + e);
        *reinterpret_cast<uint4*>(sm + A_QL + row * QK_ROW + ch * 16) =
            *reinterpret_cast<const uint4*>(g_Ql + e);
    }
    __syncthreads();

    const int mf = wid >> 2;
    const int nfb = (wid & 3) * 3;
    float sc[3][4];
#pragma unroll
    for (int j = 0; j < 3; j++)
#pragma unroll
        for (int q = 0; q < 4; q++) sc[j][q] = 0.f;

#pragma unroll
    for (int kf = 0; kf < 2; kf++) {
        uint32_t qh[4], ql[4];
        uint32_t aoff = (uint32_t)((mf * 16 + lm_row) * QK_ROW) + kf * 32 + lm_chunk;
        LDM_X4(qh, sb + A_QH + aoff);
        LDM_X4(ql, sb + A_QL + aoff);
#pragma unroll
        for (int j = 0; j < 3; j++) {
            uint32_t kk[2];
            uint32_t boff = (uint32_t)(((nfb + j) * 8 + (lane & 7)) * QK_ROW) + kf * 32 +
                            (((lane >> 3) & 1) * 16);
            LDM_X2(kk, sb + A_K + boff);
            MMA_F16(sc[j], qh, kk);
            MMA_F16(sc[j], ql, kk);
        }
    }

    const float rsC = 0.17677669529663689f;
    const int r0 = mf * 16 + (lane >> 2);
    const int r1 = r0 + 8;
    float sv[3][4];
#pragma unroll
    for (int j = 0; j < 3; j++) {
        int nb = (nfb + j) * 8 + (lane & 3) * 2;
#pragma unroll
        for (int q = 0; q < 4; q++) {
            int n = nb + (q & 1);
            int row = (q < 2) ? r0 : r1;
            int t = s0 - 32 + n;
            bool ok = (n >= row) && (n <= row + 64) && (t >= 0) && (t < S_);
            sv[j][q] = ok ? sc[j][q] * rsC : -1e30f;
        }
    }
    float m0 = -1e30f, m1 = -1e30f;
#pragma unroll
    for (int j = 0; j < 3; j++) {
        m0 = fmaxf(m0, fmaxf(sv[j][0], sv[j][1]));
        m1 = fmaxf(m1, fmaxf(sv[j][2], sv[j][3]));
    }
    m0 = fmaxf(m0, __shfl_xor_sync(0xffffffffu, m0, 1));
    m0 = fmaxf(m0, __shfl_xor_sync(0xffffffffu, m0, 2));
    m1 = fmaxf(m1, __shfl_xor_sync(0xffffffffu, m1, 1));
    m1 = fmaxf(m1, __shfl_xor_sync(0xffffffffu, m1, 2));
    if ((lane & 3) == 0) {
        red[r0 * 8 + (wid & 3)] = m0;
        red[r1 * 8 + (wid & 3)] = m1;
    }
    __syncthreads();
    float mx0 = fmaxf(fmaxf(red[r0 * 8 + 0], red[r0 * 8 + 1]),
                      fmaxf(red[r0 * 8 + 2], red[r0 * 8 + 3]));
    float mx1 = fmaxf(fmaxf(red[r1 * 8 + 0], red[r1 * 8 + 1]),
                      fmaxf(red[r1 * 8 + 2], red[r1 * 8 + 3]));
    float e[3][4], sum0 = 0.f, sum1 = 0.f;
#pragma unroll
    for (int j = 0; j < 3; j++) {
        e[j][0] = __expf(sv[j][0] - mx0);
        e[j][1] = __expf(sv[j][1] - mx0);
        e[j][2] = __expf(sv[j][2] - mx1);
        e[j][3] = __expf(sv[j][3] - mx1);
        sum0 += e[j][0] + e[j][1];
        sum1 += e[j][2] + e[j][3];
    }
    sum0 += __shfl_xor_sync(0xffffffffu, sum0, 1);
    sum0 += __shfl_xor_sync(0xffffffffu, sum0, 2);
    sum1 += __shfl_xor_sync(0xffffffffu, sum1, 1);
    sum1 += __shfl_xor_sync(0xffffffffu, sum1, 2);
    if ((lane & 3) == 0) {
        red[r0 * 8 + 4 + (wid & 3)] = sum0;
        red[r1 * 8 + 4 + (wid & 3)] = sum1;
    }
    __syncthreads();
    float inv0 = 1.f / (red[r0 * 8 + 4] + red[r0 * 8 + 5] + red[r0 * 8 + 6] + red[r0 * 8 + 7]);
    float inv1 = 1.f / (red[r1 * 8 + 4] + red[r1 * 8 + 5] + red[r1 * 8 + 6] + red[r1 * 8 + 7]);

#pragma unroll
    for (int j = 0; j < 3; j++) {
        int nb = (nfb + j) * 8 + (lane & 3) * 2;
        uint32_t h0, l0, h1, l1;
        split2h(e[j][0] * inv0, e[j][1] * inv0, h0, l0);
        split2h(e[j][2] * inv1, e[j][3] * inv1, h1, l1);
        *reinterpret_cast<uint32_t*>(sm + A_PH + r0 * VT_ROW + nb * 2) = h0;
        *reinterpret_cast<uint32_t*>(sm + A_PL + r0 * VT_ROW + nb * 2) = l0;
        *reinterpret_cast<uint32_t*>(sm + A_PH + r1 * VT_ROW + nb * 2) = h1;
        *reinterpret_cast<uint32_t*>(sm + A_PL + r1 * VT_ROW + nb * 2) = l1;
    }
    __syncthreads();

    const int nc = wid & 3;
    float oacc[4] = {0.f, 0.f, 0.f, 0.f};
#pragma unroll
    for (int kf = 0; kf < 6; kf++) {
        uint32_t ph[4], pl[4], vv[2];
        uint32_t poff = (uint32_t)((mf * 16 + lm_row) * VT_ROW) + kf * 32 + lm_chunk;
        LDM_X4(ph, sb + A_PH + poff);
        LDM_X4(pl, sb + A_PL + poff);
        uint32_t voff = (uint32_t)((kf * 16 + (lane & 15)) * QK_ROW) + nc * 16;
        LDM_X2_T(vv, sb + A_V + voff);
        MMA_F16(oacc, ph, vv);
        MMA_F16(oacc, pl, vv);
    }

    {
        int gcol = h * 32 + nc * 8 + (lane & 3) * 2;
        size_t e0 = (size_t)(b * S_ + s0 + r0) * 256 + gcol;
        size_t e1 = (size_t)(b * S_ + s0 + r1) * 256 + gcol;
        float2 gA = *reinterpret_cast<const float2*>(g_G + e0);
        float2 gB = *reinterpret_cast<const float2*>(g_G + e1);
        __half2 o0 = __floats2half2_rn(oacc[0] * gA.x, oacc[1] * gA.y);
        __half2 o1 = __floats2half2_rn(oacc[2] * gB.x, oacc[3] * gB.y);
        *reinterpret_cast<uint32_t*>(g_O + e0) = *reinterpret_cast<uint32_t*>(&o0);
        *reinterpret_cast<uint32_t*>(g_O + e1) = *reinterpret_cast<uint32_t*>(&o1);
    }
}

// ============================================================
extern "C" void kernel_launch(void* const* d_in, const int* in_sizes, int n_in,
                              void* d_out, int out_size) {
    const float* Qin = (const float*)d_in[0];
    const float* Kin = (const float*)d_in[1];
    const float* Vin = (const float*)d_in[2];
    const float* QT  = (const float*)d_in[3];
    const float* KT  = (const float*)d_in[4];
    const float* VT  = (const float*)d_in[5];
    const float* GW  = (const float*)d_in[6];
    const float* Gb  = (const float*)d_in[7];
    const float* OW  = (const float*)d_in[8];
    const float* Ob  = (const float*)d_in[9];
    float* out = (float*)d_out;

    cudaFuncSetAttribute(proj_kernel, cudaFuncAttributeMaxDynamicSharedMemorySize, SMEM_GEMM);
    cudaFuncSetAttribute(out_kernel,  cudaFuncAttributeMaxDynamicSharedMemorySize, SMEM_GEMM);

    prep_all<<<3392, 256>>>(Qin, Kin, Vin, QT, KT, VT, GW, OW);
    proj_kernel<<<dim3(4, 64, 4), 256, SMEM_GEMM>>>(Gb);
    attn_kernel<<<dim3(S_ / 32, H_, B_), 256>>>();
    out_kernel<<<dim3(4, 64, 1), 256, SMEM_GEMM>>>(Ob, out);
}